// round 1
// baseline (speedup 1.0000x reference)
#include <cuda_runtime.h>
#include <math.h>

// Problem constants
#define BB   32
#define SEQ  577
#define DIM  768
#define QKVD 2304                    // 3*DIM
#define ROWS (BB * SEQ)              // 18464

// Scratch (static device memory — allocation-guard safe)
__device__ float g_qkv[(size_t)ROWS * QKVD];        // [B*N, 3C]  ~170MB
__device__ float g_s  [(size_t)BB * SEQ * SEQ];     // scores     ~42.6MB
__device__ float g_yt [(size_t)ROWS * DIM];         // y transposed per batch [C,N] ~56.7MB

// ---------------------------------------------------------------------------
// GEMM NT: C[m,n] = alpha * sum_k A[m,k]*B[n,k]  (+bias[n])
// A row-major (lda), B row-major (ldb), both K-contiguous. Requires K%16==0,
// (k-offsets)%4==0 alignment on A/B rows (true for all call sites: K=768).
// Batched via blockIdx.z with element strides sA/sB/sC.
// Tile 128x128x16, 256 threads, 8x8 per-thread microtile.
// ---------------------------------------------------------------------------
__global__ __launch_bounds__(256) void gemm_nt(
    const float* __restrict__ A, const float* __restrict__ B,
    float* __restrict__ C, const float* __restrict__ bias,
    int M, int N, int K, int lda, int ldb, int ldc,
    long sA, long sB, long sC, float alpha)
{
    __shared__ __align__(16) float As[16][132];
    __shared__ __align__(16) float Bs[16][132];

    const int bz = blockIdx.z;
    A += (long)bz * sA;  B += (long)bz * sB;  C += (long)bz * sC;

    const int m0 = blockIdx.y * 128;
    const int n0 = blockIdx.x * 128;
    const int tid = threadIdx.x;
    const int tx = tid & 15, ty = tid >> 4;
    const int lr = tid >> 2;            // 0..63 (row within tile, 2 passes)
    const int lc = (tid & 3) << 2;      // k offset 0,4,8,12

    float acc[8][8];
#pragma unroll
    for (int i = 0; i < 8; i++)
#pragma unroll
        for (int j = 0; j < 8; j++) acc[i][j] = 0.f;

    for (int k0 = 0; k0 < K; k0 += 16) {
#pragma unroll
        for (int i = 0; i < 2; i++) {
            const int r = lr + i * 64;
            // A tile
            {
                const int gm = m0 + r;
                float4 v = make_float4(0.f, 0.f, 0.f, 0.f);
                if (gm < M) v = *(const float4*)(A + (long)gm * lda + k0 + lc);
                As[lc + 0][r] = v.x; As[lc + 1][r] = v.y;
                As[lc + 2][r] = v.z; As[lc + 3][r] = v.w;
            }
            // B tile
            {
                const int gn = n0 + r;
                float4 v = make_float4(0.f, 0.f, 0.f, 0.f);
                if (gn < N) v = *(const float4*)(B + (long)gn * ldb + k0 + lc);
                Bs[lc + 0][r] = v.x; Bs[lc + 1][r] = v.y;
                Bs[lc + 2][r] = v.z; Bs[lc + 3][r] = v.w;
            }
        }
        __syncthreads();

#pragma unroll
        for (int k = 0; k < 16; k++) {
            float4 a0 = *(const float4*)&As[k][ty * 8];
            float4 a1 = *(const float4*)&As[k][ty * 8 + 4];
            float4 b0 = *(const float4*)&Bs[k][tx * 8];
            float4 b1 = *(const float4*)&Bs[k][tx * 8 + 4];
            const float ar[8] = {a0.x, a0.y, a0.z, a0.w, a1.x, a1.y, a1.z, a1.w};
            const float br[8] = {b0.x, b0.y, b0.z, b0.w, b1.x, b1.y, b1.z, b1.w};
#pragma unroll
            for (int i = 0; i < 8; i++)
#pragma unroll
                for (int j = 0; j < 8; j++) acc[i][j] += ar[i] * br[j];
        }
        __syncthreads();
    }

    const bool vec = ((ldc & 3) == 0);
#pragma unroll
    for (int i = 0; i < 8; i++) {
        const int gm = m0 + ty * 8 + i;
        if (gm >= M) continue;
        const long base = (long)gm * ldc;
#pragma unroll
        for (int j = 0; j < 8; j += 4) {
            const int gn = n0 + tx * 8 + j;
            float r0 = acc[i][j + 0] * alpha;
            float r1 = acc[i][j + 1] * alpha;
            float r2 = acc[i][j + 2] * alpha;
            float r3 = acc[i][j + 3] * alpha;
            if (bias) {
                if (gn + 0 < N) r0 += bias[gn + 0];
                if (gn + 1 < N) r1 += bias[gn + 1];
                if (gn + 2 < N) r2 += bias[gn + 2];
                if (gn + 3 < N) r3 += bias[gn + 3];
            }
            if (vec && (gn + 3 < N)) {
                *(float4*)(C + base + gn) = make_float4(r0, r1, r2, r3);
            } else {
                if (gn + 0 < N) C[base + gn + 0] = r0;
                if (gn + 1 < N) C[base + gn + 1] = r1;
                if (gn + 2 < N) C[base + gn + 2] = r2;
                if (gn + 3 < N) C[base + gn + 3] = r3;
            }
        }
    }
}

// ---------------------------------------------------------------------------
// GEMM TN (for P@V producing the transposed Y directly):
//   C[m,n] = sum_k A[k*lda + m] * B[n*ldb + k]
// A is M-contiguous per k-row (here: V[k, c], lda=2304, m=c).
// B is K-contiguous per n-row (here: S[nseq, k], ldb=577 — odd, so scalar B
// loads; K=577 not a multiple of 16 -> zero-fill).
// C[m*ldc + n] = Yt[c, nseq].
// ---------------------------------------------------------------------------
__global__ __launch_bounds__(256) void gemm_tn(
    const float* __restrict__ A, const float* __restrict__ B,
    float* __restrict__ C,
    int M, int N, int K, int lda, int ldb, int ldc,
    long sA, long sB, long sC)
{
    __shared__ __align__(16) float As[16][132];
    __shared__ __align__(16) float Bs[16][132];

    const int bz = blockIdx.z;
    A += (long)bz * sA;  B += (long)bz * sB;  C += (long)bz * sC;

    const int m0 = blockIdx.y * 128;
    const int n0 = blockIdx.x * 128;
    const int tid = threadIdx.x;
    const int tx = tid & 15, ty = tid >> 4;
    const int lr  = tid >> 2;            // B-load row group
    const int lc  = (tid & 3) << 2;      // B-load k offset
    const int akr = tid >> 5;            // A-load k row 0..7 (2 passes)
    const int amo = (tid & 31) << 2;     // A-load m offset 0..124

    float acc[8][8];
#pragma unroll
    for (int i = 0; i < 8; i++)
#pragma unroll
        for (int j = 0; j < 8; j++) acc[i][j] = 0.f;

    for (int k0 = 0; k0 < K; k0 += 16) {
        // A tile: As[k][m] = A[(k0+k)*lda + m0+m]; m-contiguous float4
#pragma unroll
        for (int i = 0; i < 2; i++) {
            const int k = akr + i * 8;
            const int gk = k0 + k;
            float4 v = make_float4(0.f, 0.f, 0.f, 0.f);
            if (gk < K && (m0 + amo + 3) < M)
                v = *(const float4*)(A + (long)gk * lda + m0 + amo);
            *(float4*)&As[k][amo] = v;
        }
        // B tile: Bs[k][n] = B[(n0+n)*ldb + k0+k]; scalar (odd ldb, K edge)
#pragma unroll
        for (int i = 0; i < 2; i++) {
            const int r = lr + i * 64;
            const int gn = n0 + r;
            float4 v = make_float4(0.f, 0.f, 0.f, 0.f);
            if (gn < N) {
                const float* bp = B + (long)gn * ldb + k0 + lc;
                const int rem = K - (k0 + lc);
                if (rem > 0) v.x = bp[0];
                if (rem > 1) v.y = bp[1];
                if (rem > 2) v.z = bp[2];
                if (rem > 3) v.w = bp[3];
            }
            Bs[lc + 0][r] = v.x; Bs[lc + 1][r] = v.y;
            Bs[lc + 2][r] = v.z; Bs[lc + 3][r] = v.w;
        }
        __syncthreads();

#pragma unroll
        for (int k = 0; k < 16; k++) {
            float4 a0 = *(const float4*)&As[k][ty * 8];
            float4 a1 = *(const float4*)&As[k][ty * 8 + 4];
            float4 b0 = *(const float4*)&Bs[k][tx * 8];
            float4 b1 = *(const float4*)&Bs[k][tx * 8 + 4];
            const float ar[8] = {a0.x, a0.y, a0.z, a0.w, a1.x, a1.y, a1.z, a1.w};
            const float br[8] = {b0.x, b0.y, b0.z, b0.w, b1.x, b1.y, b1.z, b1.w};
#pragma unroll
            for (int i = 0; i < 8; i++)
#pragma unroll
                for (int j = 0; j < 8; j++) acc[i][j] += ar[i] * br[j];
        }
        __syncthreads();
    }

#pragma unroll
    for (int i = 0; i < 8; i++) {
        const int gm = m0 + ty * 8 + i;
        if (gm >= M) continue;
        const long base = (long)gm * ldc;
#pragma unroll
        for (int j = 0; j < 8; j++) {
            const int gn = n0 + tx * 8 + j;
            if (gn < N) C[base + gn] = acc[i][j];
        }
    }
}

// ---------------------------------------------------------------------------
// Row softmax over g_s (ROWS rows of length SEQ, contiguous) + token-attn
// extraction: tok[b*576 + c-1] = attn[b, row 0, c] for c in [1,577).
// ---------------------------------------------------------------------------
__global__ __launch_bounds__(256) void softmax_kernel(
    float* __restrict__ S, float* __restrict__ tok)
{
    const int row = blockIdx.x;                 // 0..ROWS-1
    float* p = S + (long)row * SEQ;
    const int tid = threadIdx.x;                // 256 threads

    __shared__ float red[256];

    float v[3];
    float m = -1e30f;
#pragma unroll
    for (int i = 0; i < 3; i++) {
        const int c = tid + i * 256;
        v[i] = (c < SEQ) ? p[c] : -1e30f;
        m = fmaxf(m, v[i]);
    }
    red[tid] = m; __syncthreads();
    for (int s = 128; s > 0; s >>= 1) {
        if (tid < s) red[tid] = fmaxf(red[tid], red[tid + s]);
        __syncthreads();
    }
    m = red[0];
    __syncthreads();

    float sum = 0.f;
#pragma unroll
    for (int i = 0; i < 3; i++) {
        const int c = tid + i * 256;
        if (c < SEQ) { v[i] = __expf(v[i] - m); sum += v[i]; }
    }
    red[tid] = sum; __syncthreads();
    for (int s = 128; s > 0; s >>= 1) {
        if (tid < s) red[tid] += red[tid + s];
        __syncthreads();
    }
    const float inv = 1.0f / red[0];

    const bool tokrow = ((row % SEQ) == 0);
    const int b = row / SEQ;
#pragma unroll
    for (int i = 0; i < 3; i++) {
        const int c = tid + i * 256;
        if (c < SEQ) {
            const float o = v[i] * inv;
            p[c] = o;
            if (tokrow && c >= 1) tok[(long)b * (SEQ - 1) + (c - 1)] = o;
        }
    }
}

// ---------------------------------------------------------------------------
extern "C" void kernel_launch(void* const* d_in, const int* in_sizes, int n_in,
                              void* d_out, int out_size)
{
    const float* x      = (const float*)d_in[0];   // [32,577,768]
    const float* w_qkv  = (const float*)d_in[1];   // [2304,768]
    const float* w_proj = (const float*)d_in[2];   // [768,768]
    const float* b_proj = (const float*)d_in[3];   // [768]
    float* out = (float*)d_out;                    // [32,577,768]
    float* tok = out + (size_t)ROWS * DIM;         // [32,1,24,24]

    float *qkv, *s, *yt;
    cudaGetSymbolAddress((void**)&qkv, g_qkv);
    cudaGetSymbolAddress((void**)&s,   g_s);
    cudaGetSymbolAddress((void**)&yt,  g_yt);

    const float scale = 1.0f / sqrtf((float)DIM);
    const dim3 blk(256);

    // 1) QKV = X @ Wqkv^T : [18464,768] x [2304,768]^T -> [18464,2304]
    {
        dim3 grid(QKVD / 128, (ROWS + 127) / 128, 1);
        gemm_nt<<<grid, blk>>>(x, w_qkv, qkv, nullptr,
                               ROWS, QKVD, DIM, DIM, DIM, QKVD,
                               0, 0, 0, 1.0f);
    }
    // 2) S[b] = scale * Q_b @ K_b^T : batched [577,768] x [577,768]^T
    {
        dim3 grid((SEQ + 127) / 128, (SEQ + 127) / 128, BB);
        gemm_nt<<<grid, blk>>>(qkv + 0, qkv + DIM, s, nullptr,
                               SEQ, SEQ, DIM, QKVD, QKVD, SEQ,
                               (long)SEQ * QKVD, (long)SEQ * QKVD,
                               (long)SEQ * SEQ, scale);
    }
    // 3) softmax rows + token-attn extraction
    softmax_kernel<<<ROWS, blk>>>(s, tok);

    // 4) Yt[b][c,n] = sum_k S[b][n,k] * V[b][k,c]  (直接 transposed layout)
    {
        dim3 grid((SEQ + 127) / 128, DIM / 128, BB);
        gemm_tn<<<grid, blk>>>(qkv + 2 * DIM, s, yt,
                               DIM, SEQ, SEQ, QKVD, SEQ, SEQ,
                               (long)SEQ * QKVD, (long)SEQ * SEQ,
                               (long)DIM * SEQ);
    }
    // 5) out = Y2 @ Wproj^T + b : [18464,768] x [768,768]^T
    //    (Yt flat per batch IS y2[b] row-major — the reference transpose+reshape
    //     is a pure reinterpretation of this buffer)
    {
        dim3 grid(DIM / 128, (ROWS + 127) / 128, 1);
        gemm_nt<<<grid, blk>>>(yt, w_proj, out, b_proj,
                               ROWS, DIM, DIM, DIM, DIM, DIM,
                               0, 0, 0, 1.0f);
    }
}

// round 4
// speedup vs baseline: 2.3429x; 2.3429x over previous
#include <cuda_runtime.h>
#include <cstdint>
#include <math.h>

#define BB   32
#define SEQ  577
#define DIM  768
#define QKVD 2304
#define ROWS (BB * SEQ)      // 18464
#define SPAD 640             // padded K for PV

// ---------------- scratch ----------------
__device__ float g_qkv[(size_t)ROWS * QKVD];
__device__ float g_s  [(size_t)BB * SEQ * SPAD];
__device__ float g_vt [(size_t)BB * DIM * SPAD];
__device__ float g_yt [(size_t)BB * DIM * SEQ];

// ---------------- helpers ----------------
__device__ __forceinline__ uint32_t smem_u32(const void* p) {
    uint32_t a;
    asm("{ .reg .u64 t; cvta.to.shared.u64 t, %1; cvt.u32.u64 %0, t; }"
        : "=r"(a) : "l"(p));
    return a;
}
__device__ __forceinline__ void cpa16(uint32_t dst, const float* src, bool ok) {
    int sz = ok ? 16 : 0;
    asm volatile("cp.async.cg.shared.global [%0], [%1], 16, %2;"
                 :: "r"(dst), "l"(src), "r"(sz));
}
__device__ __forceinline__ uint32_t f2tf(uint32_t x) {
    uint32_t y;
    asm("cvt.rna.tf32.f32 %0, %1;" : "=r"(y) : "f"(__uint_as_float(x)));
    return y;
}
__device__ __forceinline__ void ldsm4(uint32_t a, uint32_t* r) {
    asm volatile("ldmatrix.sync.aligned.m8n8.x4.shared.b16 {%0,%1,%2,%3}, [%4];"
                 : "=r"(r[0]), "=r"(r[1]), "=r"(r[2]), "=r"(r[3]) : "r"(a));
}
__device__ __forceinline__ void ldsm2(uint32_t a, uint32_t* r) {
    asm volatile("ldmatrix.sync.aligned.m8n8.x2.shared.b16 {%0,%1}, [%2];"
                 : "=r"(r[0]), "=r"(r[1]) : "r"(a));
}
__device__ __forceinline__ void mma8(float* d, const uint32_t* a, const uint32_t* b) {
    asm volatile(
        "mma.sync.aligned.m16n8k8.row.col.f32.tf32.tf32.f32 "
        "{%0,%1,%2,%3}, {%4,%5,%6,%7}, {%8,%9}, {%0,%1,%2,%3};"
        : "+f"(d[0]), "+f"(d[1]), "+f"(d[2]), "+f"(d[3])
        : "r"(a[0]), "r"(a[1]), "r"(a[2]), "r"(a[3]), "r"(b[0]), "r"(b[1]));
}

// ---------------- tiling ----------------
#define BK 32                         // floats (128 bytes)
#define STAGE_A 16384                 // 128 rows * 128B
#define STAGE_BYTES 32768             // A + B
#define NSTAGE 3
#define TC_SMEM (NSTAGE * STAGE_BYTES)

// stage a 128-row x 32-float tile (A at +0, B at +16384), SW128-XOR swizzle
__device__ __forceinline__ void fill_stage(
    const float* __restrict__ A, const float* __restrict__ B,
    int M, int N, int lda, int ldb, int m0, int n0, int k0,
    uint32_t st, int tid)
{
    const int q = tid & 7;            // 16B chunk within the 128B row: floats q*4
    const int r0 = tid >> 3;          // 0..31
    const int swq = (q ^ (r0 & 7)) << 4;
#pragma unroll
    for (int p = 0; p < 4; p++) {
        const int r = r0 + p * 32;
        {   // A
            const int gr = m0 + r;
            const bool ok = gr < M;
            cpa16(st + r * 128 + swq, A + (long)(ok ? gr : 0) * lda + k0 + q * 4, ok);
        }
        {   // B
            const int gr = n0 + r;
            const bool ok = gr < N;
            cpa16(st + STAGE_A + r * 128 + swq,
                  B + (long)(ok ? gr : 0) * ldb + k0 + q * 4, ok);
        }
    }
}

// ---------------------------------------------------------------------------
// NT GEMM via mma.sync tf32:  C[m,n] = alpha * sum_k A[m,k]*B[n,k] (+bias[n])
// K % 32 == 0; lda/ldb % 4 == 0. Batched via blockIdx.z.
// ---------------------------------------------------------------------------
__global__ __launch_bounds__(256) void gemm_tc(
    const float* __restrict__ A, const float* __restrict__ B,
    float* __restrict__ C, const float* __restrict__ bias,
    int M, int N, int K, int lda, int ldb, int ldc,
    long sA, long sB, long sC, float alpha)
{
    extern __shared__ char smem[];
    const uint32_t sb = smem_u32(smem);
    const int tid = threadIdx.x;
    const int wid = tid >> 5, lane = tid & 31;
    const int wm = wid & 1, wn = wid >> 1;      // warp tile 64(m) x 32(n)

    const int bz = blockIdx.z;
    A += (long)bz * sA;  B += (long)bz * sB;  C += (long)bz * sC;
    const int m0 = blockIdx.y * 128;
    const int n0 = blockIdx.x * 128;
    const int KT = K >> 5;

    // ldmatrix per-thread addressing
    const int a_row16 = ((lane >> 3) & 1) * 8 + (lane & 7);
    const int a_qsel  = lane >> 4;
    const int l15 = lane & 15;
    const int b_row8 = l15 & 7;
    const int b_qsel = l15 >> 3;

    float acc[4][4][4];
#pragma unroll
    for (int i = 0; i < 4; i++)
#pragma unroll
        for (int j = 0; j < 4; j++)
#pragma unroll
            for (int r = 0; r < 4; r++) acc[i][j][r] = 0.f;

    // prologue: stages 0 and 1
    fill_stage(A, B, M, N, lda, ldb, m0, n0, 0, sb, tid);
    asm volatile("cp.async.commit_group;" ::: "memory");
    if (KT > 1)
        fill_stage(A, B, M, N, lda, ldb, m0, n0, 32, sb + STAGE_BYTES, tid);
    asm volatile("cp.async.commit_group;" ::: "memory");

    for (int kt = 0; kt < KT; kt++) {
        asm volatile("cp.async.wait_group 1;" ::: "memory");
        __syncthreads();

        const int fs = kt + 2;
        if (fs < KT)
            fill_stage(A, B, M, N, lda, ldb, m0, n0, fs * 32,
                       sb + (fs % NSTAGE) * STAGE_BYTES, tid);
        asm volatile("cp.async.commit_group;" ::: "memory");

        const uint32_t ab = sb + (kt % NSTAGE) * STAGE_BYTES;
        const uint32_t bb = ab + STAGE_A;

#pragma unroll
        for (int s = 0; s < 4; s++) {
            uint32_t af[4][4], bf[4][2];
#pragma unroll
            for (int mt = 0; mt < 4; mt++) {
                const int row = wm * 64 + mt * 16 + a_row16;
                const int quad = 2 * s + a_qsel;
                ldsm4(ab + row * 128 + ((quad ^ (row & 7)) << 4), af[mt]);
#pragma unroll
                for (int r = 0; r < 4; r++) af[mt][r] = f2tf(af[mt][r]);
            }
#pragma unroll
            for (int nt = 0; nt < 4; nt++) {
                const int row = wn * 32 + nt * 8 + b_row8;
                const int quad = 2 * s + b_qsel;
                ldsm2(bb + row * 128 + ((quad ^ (row & 7)) << 4), bf[nt]);
                bf[nt][0] = f2tf(bf[nt][0]);
                bf[nt][1] = f2tf(bf[nt][1]);
            }
#pragma unroll
            for (int mt = 0; mt < 4; mt++)
#pragma unroll
                for (int nt = 0; nt < 4; nt++)
                    mma8(acc[mt][nt], af[mt], bf[nt]);
        }
        __syncthreads();
    }

    // epilogue
    const int r4 = lane >> 2, cp2 = (lane & 3) * 2;
    const bool vec = ((ldc & 1) == 0);
#pragma unroll
    for (int mt = 0; mt < 4; mt++) {
#pragma unroll
        for (int half = 0; half < 2; half++) {
            const int m = m0 + wm * 64 + mt * 16 + r4 + half * 8;
            if (m >= M) continue;
            const long base = (long)m * ldc;
#pragma unroll
            for (int nt = 0; nt < 4; nt++) {
                const int n = n0 + wn * 32 + nt * 8 + cp2;
                if (n >= N) continue;
                float v0 = acc[mt][nt][half * 2 + 0] * alpha;
                float v1 = acc[mt][nt][half * 2 + 1] * alpha;
                if (bias) {
                    v0 += bias[n];
                    if (n + 1 < N) v1 += bias[n + 1];
                }
                if (vec && (n + 1 < N)) {
                    *(float2*)(C + base + n) = make_float2(v0, v1);
                } else {
                    C[base + n] = v0;
                    if (n + 1 < N) C[base + n + 1] = v1;
                }
            }
        }
    }
}

// ---------------------------------------------------------------------------
// softmax rows (stride SPAD) + token-attn + zero pad
// ---------------------------------------------------------------------------
__global__ __launch_bounds__(256) void softmax_kernel(float* __restrict__ S,
                                                      float* __restrict__ tok) {
    const int row = blockIdx.x;
    float* p = S + (long)row * SPAD;
    const int tid = threadIdx.x;
    __shared__ float red[256];

    float v[3];
    float m = -1e30f;
#pragma unroll
    for (int i = 0; i < 3; i++) {
        const int c = tid + i * 256;
        v[i] = (c < SEQ) ? p[c] : -1e30f;
        m = fmaxf(m, v[i]);
    }
    red[tid] = m; __syncthreads();
    for (int s = 128; s > 0; s >>= 1) {
        if (tid < s) red[tid] = fmaxf(red[tid], red[tid + s]);
        __syncthreads();
    }
    m = red[0];
    __syncthreads();

    float sum = 0.f;
#pragma unroll
    for (int i = 0; i < 3; i++) {
        const int c = tid + i * 256;
        if (c < SEQ) { v[i] = __expf(v[i] - m); sum += v[i]; }
    }
    red[tid] = sum; __syncthreads();
    for (int s = 128; s > 0; s >>= 1) {
        if (tid < s) red[tid] += red[tid + s];
        __syncthreads();
    }
    const float inv = 1.0f / red[0];

    const bool tokrow = ((row % SEQ) == 0);
    const int b = row / SEQ;
#pragma unroll
    for (int i = 0; i < 3; i++) {
        const int c = tid + i * 256;
        if (c < SEQ) {
            const float o = v[i] * inv;
            p[c] = o;
            if (tokrow && c >= 1) tok[(long)b * (SEQ - 1) + (c - 1)] = o;
        } else if (c < SPAD) {
            p[c] = 0.f;
        }
    }
}

// V[b][k][c] -> Vt[b][c][k] (ld SPAD, zero pad k >= SEQ)
__global__ void transpose_v(const float* __restrict__ qkv, float* __restrict__ vt) {
    __shared__ float t[32][33];
    const int b = blockIdx.z;
    const int k0 = blockIdx.x * 32, c0 = blockIdx.y * 32;
    const int tx = threadIdx.x, ty = threadIdx.y;
#pragma unroll
    for (int i = 0; i < 32; i += 8) {
        const int k = k0 + ty + i, c = c0 + tx;
        float v = 0.f;
        if (k < SEQ) v = qkv[((long)(b * SEQ + k)) * QKVD + 2 * DIM + c];
        t[ty + i][tx] = v;
    }
    __syncthreads();
#pragma unroll
    for (int i = 0; i < 32; i += 8) {
        const int c = c0 + ty + i, k = k0 + tx;
        vt[(long)b * DIM * SPAD + (long)c * SPAD + k] = t[tx][ty + i];
    }
}

// ---------------------------------------------------------------------------
extern "C" void kernel_launch(void* const* d_in, const int* in_sizes, int n_in,
                              void* d_out, int out_size)
{
    const float* x      = (const float*)d_in[0];
    const float* w_qkv  = (const float*)d_in[1];
    const float* w_proj = (const float*)d_in[2];
    const float* b_proj = (const float*)d_in[3];
    float* out = (float*)d_out;
    float* tok = out + (size_t)ROWS * DIM;

    float *qkv, *s, *vt, *yt;
    cudaGetSymbolAddress((void**)&qkv, g_qkv);
    cudaGetSymbolAddress((void**)&s,   g_s);
    cudaGetSymbolAddress((void**)&vt,  g_vt);
    cudaGetSymbolAddress((void**)&yt,  g_yt);

    cudaFuncSetAttribute(gemm_tc, cudaFuncAttributeMaxDynamicSharedMemorySize, TC_SMEM);

    const float scale = 1.0f / sqrtf((float)DIM);

    // 1) QKV = X @ Wqkv^T
    gemm_tc<<<dim3(QKVD / 128, (ROWS + 127) / 128, 1), 256, TC_SMEM>>>(
        x, w_qkv, qkv, nullptr, ROWS, QKVD, DIM, DIM, DIM, QKVD, 0, 0, 0, 1.0f);

    // 2) Vt = transpose(V), zero K-pad
    transpose_v<<<dim3(SPAD / 32, DIM / 32, BB), dim3(32, 8)>>>(qkv, vt);

    // 3) S[b] = scale * Q_b @ K_b^T
    gemm_tc<<<dim3((SEQ + 127) / 128, (SEQ + 127) / 128, BB), 256, TC_SMEM>>>(
        qkv, qkv + DIM, s, nullptr, SEQ, SEQ, DIM, QKVD, QKVD, SPAD,
        (long)SEQ * QKVD, (long)SEQ * QKVD, (long)SEQ * SPAD, scale);

    // 4) softmax + token-attn + pad
    softmax_kernel<<<ROWS, 256>>>(s, tok);

    // 5) yt[c,n] = sum_k Vt[c,k] * P[n,k]   (NT; writes transposed layout directly)
    gemm_tc<<<dim3((SEQ + 127) / 128, DIM / 128, BB), 256, TC_SMEM>>>(
        vt, s, yt, nullptr, DIM, SEQ, SPAD, SPAD, SPAD, SEQ,
        (long)DIM * SPAD, (long)SEQ * SPAD, (long)DIM * SEQ, 1.0f);

    // 6) out = Y2 @ Wproj^T + b   (yt flat == reference transpose+reshape)
    gemm_tc<<<dim3(DIM / 128, (ROWS + 127) / 128, 1), 256, TC_SMEM>>>(
        yt, w_proj, out, b_proj, ROWS, DIM, DIM, DIM, DIM, DIM, 0, 0, 0, 1.0f);
}

// round 5
// speedup vs baseline: 5.5313x; 2.3609x over previous
#include <cuda_runtime.h>
#include <cuda_fp16.h>
#include <cstdint>
#include <math.h>

#define BB   32
#define SEQ  577
#define DIM  768
#define QKVD 2304
#define ROWS (BB * SEQ)      // 18464
#define SPAD 640

// ---------------- scratch ----------------
__device__ __half g_xh  [(size_t)ROWS * DIM];
__device__ __half g_wqh [(size_t)QKVD * DIM];
__device__ __half g_wph [(size_t)DIM * DIM];
__device__ __half g_qkvh[(size_t)ROWS * QKVD];
__device__ float  g_s   [(size_t)BB * SEQ * SPAD];
__device__ __half g_p   [(size_t)BB * SEQ * SPAD];
__device__ __half g_vt  [(size_t)BB * DIM * SPAD];
__device__ __half g_yt  [(size_t)BB * DIM * SEQ];

// ---------------- helpers ----------------
__device__ __forceinline__ uint32_t smem_u32(const void* p) {
    uint32_t a;
    asm("{ .reg .u64 t; cvta.to.shared.u64 t, %1; cvt.u32.u64 %0, t; }"
        : "=r"(a) : "l"(p));
    return a;
}
__device__ __forceinline__ void cpa16(uint32_t dst, const __half* src, bool ok) {
    int sz = ok ? 16 : 0;
    asm volatile("cp.async.cg.shared.global [%0], [%1], 16, %2;"
                 :: "r"(dst), "l"(src), "r"(sz));
}
__device__ __forceinline__ void ldsm4(uint32_t a, uint32_t* r) {
    asm volatile("ldmatrix.sync.aligned.m8n8.x4.shared.b16 {%0,%1,%2,%3}, [%4];"
                 : "=r"(r[0]), "=r"(r[1]), "=r"(r[2]), "=r"(r[3]) : "r"(a));
}
__device__ __forceinline__ void ldsm2(uint32_t a, uint32_t* r) {
    asm volatile("ldmatrix.sync.aligned.m8n8.x2.shared.b16 {%0,%1}, [%2];"
                 : "=r"(r[0]), "=r"(r[1]) : "r"(a));
}
__device__ __forceinline__ void mma16(float* d, const uint32_t* a, const uint32_t* b) {
    asm volatile(
        "mma.sync.aligned.m16n8k16.row.col.f32.f16.f16.f32 "
        "{%0,%1,%2,%3}, {%4,%5,%6,%7}, {%8,%9}, {%0,%1,%2,%3};"
        : "+f"(d[0]), "+f"(d[1]), "+f"(d[2]), "+f"(d[3])
        : "r"(a[0]), "r"(a[1]), "r"(a[2]), "r"(a[3]), "r"(b[0]), "r"(b[1]));
}

// ---------------- tiling ----------------
// BK = 64 halves (128B rows). Stage: 128 rows x 128B per operand.
#define STAGE_A 16384
#define STAGE_BYTES 32768
#define NSTAGE 3
#define TC_SMEM (NSTAGE * STAGE_BYTES)

__device__ __forceinline__ void fill_stage(
    const __half* __restrict__ A, const __half* __restrict__ B,
    int M, int N, int lda, int ldb, int m0, int n0, int k0,
    uint32_t st, int tid)
{
    const int q = tid & 7;            // 16B chunk (8 halves): halves q*8
    const int r0 = tid >> 3;          // 0..31
    const int swq = (q ^ (r0 & 7)) << 4;
#pragma unroll
    for (int p = 0; p < 4; p++) {
        const int r = r0 + p * 32;
        {
            const int gr = m0 + r;
            const bool ok = gr < M;
            cpa16(st + r * 128 + swq, A + (long)(ok ? gr : 0) * lda + k0 + q * 8, ok);
        }
        {
            const int gr = n0 + r;
            const bool ok = gr < N;
            cpa16(st + STAGE_A + r * 128 + swq,
                  B + (long)(ok ? gr : 0) * ldb + k0 + q * 8, ok);
        }
    }
}

// ---------------------------------------------------------------------------
// NT GEMM, fp16 inputs, fp32 accum:
//   C[m,n] = alpha * sum_k A[m,k]*B[n,k] (+bias[n])
// outHalf=0: C is float. outHalf=1: C is __half (bias ignored).
// K % 64 == 0; lda, ldb % 8 == 0 (halves). Batched via blockIdx.z.
// ---------------------------------------------------------------------------
__global__ __launch_bounds__(256) void gemm_h(
    const __half* __restrict__ A, const __half* __restrict__ B,
    void* __restrict__ Cv, const float* __restrict__ bias,
    int M, int N, int K, int lda, int ldb, int ldc,
    long sA, long sB, long sC, float alpha, int outHalf)
{
    extern __shared__ char smem[];
    const uint32_t sb = smem_u32(smem);
    const int tid = threadIdx.x;
    const int wid = tid >> 5, lane = tid & 31;
    const int wm = wid & 1, wn = wid >> 1;      // warp tile 64(m) x 32(n)

    const int bz = blockIdx.z;
    A += (long)bz * sA;  B += (long)bz * sB;
    const int m0 = blockIdx.y * 128;
    const int n0 = blockIdx.x * 128;
    const int KT = K >> 6;                      // 64 halves per tile

    // ldmatrix addressing
    const int a_row = lane & 15;                // rows 0-15 within m16 tile
    const int a_co  = lane >> 4;                // +16B for k8-15 halves
    const int b_row = lane & 7;
    const int b_co  = (lane >> 3) & 1;

    float acc[4][4][4];
#pragma unroll
    for (int i = 0; i < 4; i++)
#pragma unroll
        for (int j = 0; j < 4; j++)
#pragma unroll
            for (int r = 0; r < 4; r++) acc[i][j][r] = 0.f;

    fill_stage(A, B, M, N, lda, ldb, m0, n0, 0, sb, tid);
    asm volatile("cp.async.commit_group;" ::: "memory");
    if (KT > 1)
        fill_stage(A, B, M, N, lda, ldb, m0, n0, 64, sb + STAGE_BYTES, tid);
    asm volatile("cp.async.commit_group;" ::: "memory");

    for (int kt = 0; kt < KT; kt++) {
        asm volatile("cp.async.wait_group 1;" ::: "memory");
        __syncthreads();

        const int fs = kt + 2;
        if (fs < KT)
            fill_stage(A, B, M, N, lda, ldb, m0, n0, fs * 64,
                       sb + (fs % NSTAGE) * STAGE_BYTES, tid);
        asm volatile("cp.async.commit_group;" ::: "memory");

        const uint32_t ab = sb + (kt % NSTAGE) * STAGE_BYTES;
        const uint32_t bb = ab + STAGE_A;

#pragma unroll
        for (int s = 0; s < 4; s++) {           // 4 x K16 within 64-half tile
            uint32_t af[4][4], bf[4][2];
#pragma unroll
            for (int mt = 0; mt < 4; mt++) {
                const int row = wm * 64 + mt * 16 + a_row;
                const int ch = 2 * s + a_co;
                ldsm4(ab + row * 128 + ((ch ^ (row & 7)) << 4), af[mt]);
            }
#pragma unroll
            for (int nt = 0; nt < 4; nt++) {
                const int row = wn * 32 + nt * 8 + b_row;
                const int ch = 2 * s + b_co;
                ldsm2(bb + row * 128 + ((ch ^ (row & 7)) << 4), bf[nt]);
            }
#pragma unroll
            for (int mt = 0; mt < 4; mt++)
#pragma unroll
                for (int nt = 0; nt < 4; nt++)
                    mma16(acc[mt][nt], af[mt], bf[nt]);
        }
        __syncthreads();
    }

    // epilogue
    const int r4 = lane >> 2, cp2 = (lane & 3) * 2;
    if (outHalf) {
        __half* C = (__half*)Cv + (long)bz * sC;
        const bool vec = ((ldc & 1) == 0);
#pragma unroll
        for (int mt = 0; mt < 4; mt++)
#pragma unroll
            for (int half_ = 0; half_ < 2; half_++) {
                const int m = m0 + wm * 64 + mt * 16 + r4 + half_ * 8;
                if (m >= M) continue;
                const long base = (long)m * ldc;
#pragma unroll
                for (int nt = 0; nt < 4; nt++) {
                    const int n = n0 + wn * 32 + nt * 8 + cp2;
                    if (n >= N) continue;
                    const float v0 = acc[mt][nt][half_ * 2 + 0] * alpha;
                    const float v1 = acc[mt][nt][half_ * 2 + 1] * alpha;
                    if (vec && (n + 1 < N)) {
                        *(__half2*)(C + base + n) = __floats2half2_rn(v0, v1);
                    } else {
                        C[base + n] = __float2half_rn(v0);
                        if (n + 1 < N) C[base + n + 1] = __float2half_rn(v1);
                    }
                }
            }
    } else {
        float* C = (float*)Cv + (long)bz * sC;
#pragma unroll
        for (int mt = 0; mt < 4; mt++)
#pragma unroll
            for (int half_ = 0; half_ < 2; half_++) {
                const int m = m0 + wm * 64 + mt * 16 + r4 + half_ * 8;
                if (m >= M) continue;
                const long base = (long)m * ldc;
#pragma unroll
                for (int nt = 0; nt < 4; nt++) {
                    const int n = n0 + wn * 32 + nt * 8 + cp2;
                    if (n >= N) continue;
                    float v0 = acc[mt][nt][half_ * 2 + 0] * alpha;
                    float v1 = acc[mt][nt][half_ * 2 + 1] * alpha;
                    if (bias) {
                        v0 += bias[n];
                        if (n + 1 < N) v1 += bias[n + 1];
                    }
                    if ((ldc & 1) == 0 && (n + 1 < N)) {
                        *(float2*)(C + base + n) = make_float2(v0, v1);
                    } else {
                        C[base + n] = v0;
                        if (n + 1 < N) C[base + n + 1] = v1;
                    }
                }
            }
    }
}

// ---------------- fp32 -> fp16 conversion ----------------
__global__ void f2h_kernel(const float* __restrict__ in, __half* __restrict__ out,
                           long n) {
    const long i = ((long)blockIdx.x * blockDim.x + threadIdx.x) * 4;
    if (i + 3 < n) {
        const float4 v = *(const float4*)(in + i);
        *(__half2*)(out + i)     = __floats2half2_rn(v.x, v.y);
        *(__half2*)(out + i + 2) = __floats2half2_rn(v.z, v.w);
    } else {
        for (long j = i; j < n; j++) out[j] = __float2half_rn(in[j]);
    }
}

// ---------------- softmax: fp32 scores -> fp16 P (+pad, +token-attn) --------
__global__ __launch_bounds__(256) void softmax_kernel(
    const float* __restrict__ S, __half* __restrict__ P, float* __restrict__ tok)
{
    const int row = blockIdx.x;
    const float* p = S + (long)row * SPAD;
    __half* o = P + (long)row * SPAD;
    const int tid = threadIdx.x;
    __shared__ float red[256];

    float v[3];
    float m = -1e30f;
#pragma unroll
    for (int i = 0; i < 3; i++) {
        const int c = tid + i * 256;
        v[i] = (c < SEQ) ? p[c] : -1e30f;
        m = fmaxf(m, v[i]);
    }
    red[tid] = m; __syncthreads();
    for (int s = 128; s > 0; s >>= 1) {
        if (tid < s) red[tid] = fmaxf(red[tid], red[tid + s]);
        __syncthreads();
    }
    m = red[0];
    __syncthreads();

    float sum = 0.f;
#pragma unroll
    for (int i = 0; i < 3; i++) {
        const int c = tid + i * 256;
        if (c < SEQ) { v[i] = __expf(v[i] - m); sum += v[i]; }
    }
    red[tid] = sum; __syncthreads();
    for (int s = 128; s > 0; s >>= 1) {
        if (tid < s) red[tid] += red[tid + s];
        __syncthreads();
    }
    const float inv = 1.0f / red[0];

    const bool tokrow = ((row % SEQ) == 0);
    const int b = row / SEQ;
#pragma unroll
    for (int i = 0; i < 3; i++) {
        const int c = tid + i * 256;
        if (c < SEQ) {
            const float x = v[i] * inv;
            o[c] = __float2half_rn(x);
            if (tokrow && c >= 1) tok[(long)b * (SEQ - 1) + (c - 1)] = x;
        } else if (c < SPAD) {
            o[c] = __float2half_rn(0.f);
        }
    }
}

// V (half, inside qkvh) -> Vt[b][c][k] half, ld SPAD, zero pad
__global__ void transpose_v(const __half* __restrict__ qkvh,
                            __half* __restrict__ vt) {
    __shared__ __half t[32][34];
    const int b = blockIdx.z;
    const int k0 = blockIdx.x * 32, c0 = blockIdx.y * 32;
    const int tx = threadIdx.x, ty = threadIdx.y;
#pragma unroll
    for (int i = 0; i < 32; i += 8) {
        const int k = k0 + ty + i, c = c0 + tx;
        __half v = __float2half_rn(0.f);
        if (k < SEQ) v = qkvh[((long)(b * SEQ + k)) * QKVD + 2 * DIM + c];
        t[ty + i][tx] = v;
    }
    __syncthreads();
#pragma unroll
    for (int i = 0; i < 32; i += 8) {
        const int c = c0 + ty + i, k = k0 + tx;
        vt[(long)b * DIM * SPAD + (long)c * SPAD + k] = t[tx][ty + i];
    }
}

// ---------------------------------------------------------------------------
extern "C" void kernel_launch(void* const* d_in, const int* in_sizes, int n_in,
                              void* d_out, int out_size)
{
    const float* x      = (const float*)d_in[0];
    const float* w_qkv  = (const float*)d_in[1];
    const float* w_proj = (const float*)d_in[2];
    const float* b_proj = (const float*)d_in[3];
    float* out = (float*)d_out;
    float* tok = out + (size_t)ROWS * DIM;

    __half *xh, *wqh, *wph, *qkvh, *p, *vt, *yt;
    float *s;
    cudaGetSymbolAddress((void**)&xh,   g_xh);
    cudaGetSymbolAddress((void**)&wqh,  g_wqh);
    cudaGetSymbolAddress((void**)&wph,  g_wph);
    cudaGetSymbolAddress((void**)&qkvh, g_qkvh);
    cudaGetSymbolAddress((void**)&s,    g_s);
    cudaGetSymbolAddress((void**)&p,    g_p);
    cudaGetSymbolAddress((void**)&vt,   g_vt);
    cudaGetSymbolAddress((void**)&yt,   g_yt);

    cudaFuncSetAttribute(gemm_h, cudaFuncAttributeMaxDynamicSharedMemorySize, TC_SMEM);

    const float scale = 1.0f / sqrtf((float)DIM);

    // 0) fp32 -> fp16 conversions
    {
        const long nx = (long)ROWS * DIM;
        f2h_kernel<<<(int)((nx / 4 + 255) / 256), 256>>>(x, xh, nx);
        const long nw = (long)QKVD * DIM;
        f2h_kernel<<<(int)((nw / 4 + 255) / 256), 256>>>(w_qkv, wqh, nw);
        const long np = (long)DIM * DIM;
        f2h_kernel<<<(int)((np / 4 + 255) / 256), 256>>>(w_proj, wph, np);
    }

    // 1) QKV (half out)
    gemm_h<<<dim3(QKVD / 128, (ROWS + 127) / 128, 1), 256, TC_SMEM>>>(
        xh, wqh, qkvh, nullptr, ROWS, QKVD, DIM, DIM, DIM, QKVD,
        0, 0, 0, 1.0f, 1);

    // 2) Vt = transpose(V), zero pad
    transpose_v<<<dim3(SPAD / 32, DIM / 32, BB), dim3(32, 8)>>>(qkvh, vt);

    // 3) S[b] = scale * Q K^T  (float out)
    gemm_h<<<dim3((SEQ + 127) / 128, (SEQ + 127) / 128, BB), 256, TC_SMEM>>>(
        qkvh, qkvh + DIM, s, nullptr, SEQ, SEQ, DIM, QKVD, QKVD, SPAD,
        (long)SEQ * QKVD, (long)SEQ * QKVD, (long)SEQ * SPAD, scale, 0);

    // 4) softmax -> fp16 P
    softmax_kernel<<<ROWS, 256>>>(s, p, tok);

    // 5) yt[c,n] = sum_k Vt[c,k] * P[n,k]  (half out, writes transposed layout)
    gemm_h<<<dim3((SEQ + 127) / 128, DIM / 128, BB), 256, TC_SMEM>>>(
        vt, p, yt, nullptr, DIM, SEQ, SPAD, SPAD, SPAD, SEQ,
        (long)DIM * SPAD, (long)SEQ * SPAD, (long)DIM * SEQ, 1.0f, 1);

    // 6) out = Y2 @ Wproj^T + bias  (float out; yt flat == reference reshape)
    gemm_h<<<dim3(DIM / 128, (ROWS + 127) / 128, 1), 256, TC_SMEM>>>(
        yt, wph, out, b_proj, ROWS, DIM, DIM, DIM, DIM, DIM,
        0, 0, 0, 1.0f, 0);
}

// round 6
// speedup vs baseline: 6.3601x; 1.1498x over previous
#include <cuda_runtime.h>
#include <cuda_fp16.h>
#include <cstdint>
#include <math.h>

#define BB   32
#define SEQ  577
#define DIM  768
#define QKVD 2304
#define ROWS (BB * SEQ)      // 18464
#define SPAD 640

// ---------------- scratch ----------------
__device__ __half g_xh  [(size_t)ROWS * DIM];
__device__ __half g_wqh [(size_t)QKVD * DIM];
__device__ __half g_wph [(size_t)DIM * DIM];
__device__ __half g_qkvh[(size_t)ROWS * QKVD];
__device__ float  g_s   [(size_t)BB * SEQ * SPAD];
__device__ __half g_p   [(size_t)BB * SEQ * SPAD];
__device__ __half g_vt  [(size_t)BB * DIM * SPAD];
__device__ __half g_yt  [(size_t)BB * DIM * SEQ];

// ---------------- helpers ----------------
__device__ __forceinline__ uint32_t smem_u32(const void* p) {
    uint32_t a;
    asm("{ .reg .u64 t; cvta.to.shared.u64 t, %1; cvt.u32.u64 %0, t; }"
        : "=r"(a) : "l"(p));
    return a;
}
__device__ __forceinline__ void cpa16(uint32_t dst, const __half* src, bool ok) {
    int sz = ok ? 16 : 0;
    asm volatile("cp.async.cg.shared.global [%0], [%1], 16, %2;"
                 :: "r"(dst), "l"(src), "r"(sz));
}
__device__ __forceinline__ void ldsm4(uint32_t a, uint32_t* r) {
    asm volatile("ldmatrix.sync.aligned.m8n8.x4.shared.b16 {%0,%1,%2,%3}, [%4];"
                 : "=r"(r[0]), "=r"(r[1]), "=r"(r[2]), "=r"(r[3]) : "r"(a));
}
__device__ __forceinline__ void ldsm2(uint32_t a, uint32_t* r) {
    asm volatile("ldmatrix.sync.aligned.m8n8.x2.shared.b16 {%0,%1}, [%2];"
                 : "=r"(r[0]), "=r"(r[1]) : "r"(a));
}
__device__ __forceinline__ void mma16(float* d, const uint32_t* a, const uint32_t* b) {
    asm volatile(
        "mma.sync.aligned.m16n8k16.row.col.f32.f16.f16.f32 "
        "{%0,%1,%2,%3}, {%4,%5,%6,%7}, {%8,%9}, {%0,%1,%2,%3};"
        : "+f"(d[0]), "+f"(d[1]), "+f"(d[2]), "+f"(d[3])
        : "r"(a[0]), "r"(a[1]), "r"(a[2]), "r"(a[3]), "r"(b[0]), "r"(b[1]));
}

// ---------------- tiling ----------------
#define STAGE_A 16384
#define STAGE_BYTES 32768
#define NSTAGE 3
#define TC_SMEM (NSTAGE * STAGE_BYTES)   // 96KB -> 2 CTAs/SM = 192KB

__device__ __forceinline__ void fill_stage(
    const __half* __restrict__ A, const __half* __restrict__ B,
    int M, int N, int lda, int ldb, int m0, int n0, int k0,
    uint32_t st, int tid)
{
    const int q = tid & 7;
    const int r0 = tid >> 3;
    const int swq = (q ^ (r0 & 7)) << 4;
#pragma unroll
    for (int p = 0; p < 4; p++) {
        const int r = r0 + p * 32;
        {
            const int gr = m0 + r;
            const bool ok = gr < M;
            cpa16(st + r * 128 + swq, A + (long)(ok ? gr : 0) * lda + k0 + q * 8, ok);
        }
        {
            const int gr = n0 + r;
            const bool ok = gr < N;
            cpa16(st + STAGE_A + r * 128 + swq,
                  B + (long)(ok ? gr : 0) * ldb + k0 + q * 8, ok);
        }
    }
}

// ---------------------------------------------------------------------------
// NT GEMM, fp16 in, fp32 accum. outHalf=0: C float (+bias); 1: C half.
// K % 64 == 0; lda, ldb % 8 == 0. Batched via blockIdx.z.
// ---------------------------------------------------------------------------
__global__ __launch_bounds__(256, 2) void gemm_h(
    const __half* __restrict__ A, const __half* __restrict__ B,
    void* __restrict__ Cv, const float* __restrict__ bias,
    int M, int N, int K, int lda, int ldb, int ldc,
    long sA, long sB, long sC, float alpha, int outHalf)
{
    extern __shared__ char smem[];
    const uint32_t sb = smem_u32(smem);
    const int tid = threadIdx.x;
    const int wid = tid >> 5, lane = tid & 31;
    const int wm = wid & 1, wn = wid >> 1;      // warp tile 64(m) x 32(n)

    const int bz = blockIdx.z;
    A += (long)bz * sA;  B += (long)bz * sB;
    const int m0 = blockIdx.y * 128;
    const int n0 = blockIdx.x * 128;
    const int KT = K >> 6;

    const int a_row = lane & 15;
    const int a_co  = lane >> 4;
    const int b_row = lane & 7;
    const int b_co  = (lane >> 3) & 1;

    // precompute swizzled smem offsets (row-dependent XOR is loop-invariant)
    uint32_t a_off[4], b_off[4];
#pragma unroll
    for (int mt = 0; mt < 4; mt++) {
        const int row = wm * 64 + mt * 16 + a_row;
        a_off[mt] = row * 128 + ((a_co ^ (row & 7)) << 4);
    }
#pragma unroll
    for (int nt = 0; nt < 4; nt++) {
        const int row = wn * 32 + nt * 8 + b_row;
        b_off[nt] = STAGE_A + row * 128 + ((b_co ^ (row & 7)) << 4);
    }

    float acc[4][4][4];
#pragma unroll
    for (int i = 0; i < 4; i++)
#pragma unroll
        for (int j = 0; j < 4; j++)
#pragma unroll
            for (int r = 0; r < 4; r++) acc[i][j][r] = 0.f;

    fill_stage(A, B, M, N, lda, ldb, m0, n0, 0, sb, tid);
    asm volatile("cp.async.commit_group;" ::: "memory");
    if (KT > 1)
        fill_stage(A, B, M, N, lda, ldb, m0, n0, 64, sb + STAGE_BYTES, tid);
    asm volatile("cp.async.commit_group;" ::: "memory");

    for (int kt = 0; kt < KT; kt++) {
        asm volatile("cp.async.wait_group 1;" ::: "memory");
        __syncthreads();

        const int fs = kt + 2;
        if (fs < KT)
            fill_stage(A, B, M, N, lda, ldb, m0, n0, fs * 64,
                       sb + (fs % NSTAGE) * STAGE_BYTES, tid);
        asm volatile("cp.async.commit_group;" ::: "memory");

        const uint32_t st = sb + (kt % NSTAGE) * STAGE_BYTES;

#pragma unroll
        for (int s = 0; s < 4; s++) {           // 4 x K16
            const uint32_t ksw = (uint32_t)(2 * s) << 4;  // chunk XOR offset
            uint32_t af[4][4], bf[4][2];
#pragma unroll
            for (int mt = 0; mt < 4; mt++)
                ldsm4(st + (a_off[mt] ^ ksw), af[mt]);
#pragma unroll
            for (int nt = 0; nt < 4; nt++)
                ldsm2(st + (b_off[nt] ^ ksw), bf[nt]);
#pragma unroll
            for (int mt = 0; mt < 4; mt++)
#pragma unroll
                for (int nt = 0; nt < 4; nt++)
                    mma16(acc[mt][nt], af[mt], bf[nt]);
        }
        __syncthreads();
    }

    // epilogue
    const int r4 = lane >> 2, cp2 = (lane & 3) * 2;
    if (outHalf) {
        __half* C = (__half*)Cv + (long)bz * sC;
        const bool vec = ((ldc & 1) == 0);
#pragma unroll
        for (int mt = 0; mt < 4; mt++)
#pragma unroll
            for (int half_ = 0; half_ < 2; half_++) {
                const int m = m0 + wm * 64 + mt * 16 + r4 + half_ * 8;
                if (m >= M) continue;
                const long base = (long)m * ldc;
#pragma unroll
                for (int nt = 0; nt < 4; nt++) {
                    const int n = n0 + wn * 32 + nt * 8 + cp2;
                    if (n >= N) continue;
                    const float v0 = acc[mt][nt][half_ * 2 + 0] * alpha;
                    const float v1 = acc[mt][nt][half_ * 2 + 1] * alpha;
                    if (vec && (n + 1 < N)) {
                        *(__half2*)(C + base + n) = __floats2half2_rn(v0, v1);
                    } else {
                        C[base + n] = __float2half_rn(v0);
                        if (n + 1 < N) C[base + n + 1] = __float2half_rn(v1);
                    }
                }
            }
    } else {
        float* C = (float*)Cv + (long)bz * sC;
#pragma unroll
        for (int mt = 0; mt < 4; mt++)
#pragma unroll
            for (int half_ = 0; half_ < 2; half_++) {
                const int m = m0 + wm * 64 + mt * 16 + r4 + half_ * 8;
                if (m >= M) continue;
                const long base = (long)m * ldc;
#pragma unroll
                for (int nt = 0; nt < 4; nt++) {
                    const int n = n0 + wn * 32 + nt * 8 + cp2;
                    if (n >= N) continue;
                    float v0 = acc[mt][nt][half_ * 2 + 0] * alpha;
                    float v1 = acc[mt][nt][half_ * 2 + 1] * alpha;
                    if (bias) {
                        v0 += bias[n];
                        if (n + 1 < N) v1 += bias[n + 1];
                    }
                    if ((ldc & 1) == 0 && (n + 1 < N)) {
                        *(float2*)(C + base + n) = make_float2(v0, v1);
                    } else {
                        C[base + n] = v0;
                        if (n + 1 < N) C[base + n + 1] = v1;
                    }
                }
            }
    }
}

// ---------------- fp32 -> fp16 ----------------
__global__ void f2h_kernel(const float* __restrict__ in, __half* __restrict__ out,
                           long n) {
    const long i = ((long)blockIdx.x * blockDim.x + threadIdx.x) * 4;
    if (i + 3 < n) {
        const float4 v = *(const float4*)(in + i);
        *(__half2*)(out + i)     = __floats2half2_rn(v.x, v.y);
        *(__half2*)(out + i + 2) = __floats2half2_rn(v.z, v.w);
    } else {
        for (long j = i; j < n; j++) out[j] = __float2half_rn(in[j]);
    }
}

// ---------------- softmax: fp32 -> fp16 P (+pad, +token-attn) ----------------
__global__ __launch_bounds__(256) void softmax_kernel(
    const float* __restrict__ S, __half* __restrict__ P, float* __restrict__ tok)
{
    const int row = blockIdx.x;
    const float* p = S + (long)row * SPAD;
    __half* o = P + (long)row * SPAD;
    const int tid = threadIdx.x;
    __shared__ float red[256];

    float v[3];
    float m = -1e30f;
#pragma unroll
    for (int i = 0; i < 3; i++) {
        const int c = tid + i * 256;
        v[i] = (c < SEQ) ? p[c] : -1e30f;
        m = fmaxf(m, v[i]);
    }
    red[tid] = m; __syncthreads();
    for (int s = 128; s > 0; s >>= 1) {
        if (tid < s) red[tid] = fmaxf(red[tid], red[tid + s]);
        __syncthreads();
    }
    m = red[0];
    __syncthreads();

    float sum = 0.f;
#pragma unroll
    for (int i = 0; i < 3; i++) {
        const int c = tid + i * 256;
        if (c < SEQ) { v[i] = __expf(v[i] - m); sum += v[i]; }
    }
    red[tid] = sum; __syncthreads();
    for (int s = 128; s > 0; s >>= 1) {
        if (tid < s) red[tid] += red[tid + s];
        __syncthreads();
    }
    const float inv = 1.0f / red[0];

    const bool tokrow = ((row % SEQ) == 0);
    const int b = row / SEQ;
#pragma unroll
    for (int i = 0; i < 3; i++) {
        const int c = tid + i * 256;
        if (c < SEQ) {
            const float x = v[i] * inv;
            o[c] = __float2half_rn(x);
            if (tokrow && c >= 1) tok[(long)b * (SEQ - 1) + (c - 1)] = x;
        } else if (c < SPAD) {
            o[c] = __float2half_rn(0.f);
        }
    }
}

// V -> Vt[b][c][k], zero pad
__global__ void transpose_v(const __half* __restrict__ qkvh,
                            __half* __restrict__ vt) {
    __shared__ __half t[32][34];
    const int b = blockIdx.z;
    const int k0 = blockIdx.x * 32, c0 = blockIdx.y * 32;
    const int tx = threadIdx.x, ty = threadIdx.y;
#pragma unroll
    for (int i = 0; i < 32; i += 8) {
        const int k = k0 + ty + i, c = c0 + tx;
        __half v = __float2half_rn(0.f);
        if (k < SEQ) v = qkvh[((long)(b * SEQ + k)) * QKVD + 2 * DIM + c];
        t[ty + i][tx] = v;
    }
    __syncthreads();
#pragma unroll
    for (int i = 0; i < 32; i += 8) {
        const int c = c0 + ty + i, k = k0 + tx;
        vt[(long)b * DIM * SPAD + (long)c * SPAD + k] = t[tx][ty + i];
    }
}

// ---------------------------------------------------------------------------
extern "C" void kernel_launch(void* const* d_in, const int* in_sizes, int n_in,
                              void* d_out, int out_size)
{
    const float* x      = (const float*)d_in[0];
    const float* w_qkv  = (const float*)d_in[1];
    const float* w_proj = (const float*)d_in[2];
    const float* b_proj = (const float*)d_in[3];
    float* out = (float*)d_out;
    float* tok = out + (size_t)ROWS * DIM;

    __half *xh, *wqh, *wph, *qkvh, *p, *vt, *yt;
    float *s;
    cudaGetSymbolAddress((void**)&xh,   g_xh);
    cudaGetSymbolAddress((void**)&wqh,  g_wqh);
    cudaGetSymbolAddress((void**)&wph,  g_wph);
    cudaGetSymbolAddress((void**)&qkvh, g_qkvh);
    cudaGetSymbolAddress((void**)&s,    g_s);
    cudaGetSymbolAddress((void**)&p,    g_p);
    cudaGetSymbolAddress((void**)&vt,   g_vt);
    cudaGetSymbolAddress((void**)&yt,   g_yt);

    cudaFuncSetAttribute(gemm_h, cudaFuncAttributeMaxDynamicSharedMemorySize, TC_SMEM);

    const float scale = 1.0f / sqrtf((float)DIM);

    {
        const long nx = (long)ROWS * DIM;
        f2h_kernel<<<(int)((nx / 4 + 255) / 256), 256>>>(x, xh, nx);
        const long nw = (long)QKVD * DIM;
        f2h_kernel<<<(int)((nw / 4 + 255) / 256), 256>>>(w_qkv, wqh, nw);
        const long np = (long)DIM * DIM;
        f2h_kernel<<<(int)((np / 4 + 255) / 256), 256>>>(w_proj, wph, np);
    }

    // 1) QKV (half out)
    gemm_h<<<dim3(QKVD / 128, (ROWS + 127) / 128, 1), 256, TC_SMEM>>>(
        xh, wqh, qkvh, nullptr, ROWS, QKVD, DIM, DIM, DIM, QKVD,
        0, 0, 0, 1.0f, 1);

    // 2) Vt
    transpose_v<<<dim3(SPAD / 32, DIM / 32, BB), dim3(32, 8)>>>(qkvh, vt);

    // 3) S = scale * Q K^T (float out)
    gemm_h<<<dim3((SEQ + 127) / 128, (SEQ + 127) / 128, BB), 256, TC_SMEM>>>(
        qkvh, qkvh + DIM, s, nullptr, SEQ, SEQ, DIM, QKVD, QKVD, SPAD,
        (long)SEQ * QKVD, (long)SEQ * QKVD, (long)SEQ * SPAD, scale, 0);

    // 4) softmax -> fp16 P
    softmax_kernel<<<ROWS, 256>>>(s, p, tok);

    // 5) yt = Vt @ P^T (half out, transposed layout direct)
    gemm_h<<<dim3((SEQ + 127) / 128, DIM / 128, BB), 256, TC_SMEM>>>(
        vt, p, yt, nullptr, DIM, SEQ, SPAD, SPAD, SPAD, SEQ,
        (long)DIM * SPAD, (long)SEQ * SPAD, (long)DIM * SEQ, 1.0f, 1);

    // 6) out = Y2 @ Wproj^T + bias (float out)
    gemm_h<<<dim3(DIM / 128, (ROWS + 127) / 128, 1), 256, TC_SMEM>>>(
        yt, wph, out, b_proj, ROWS, DIM, DIM, DIM, DIM, DIM,
        0, 0, 0, 1.0f, 0);
}

// round 7
// speedup vs baseline: 6.6697x; 1.0487x over previous
#include <cuda_runtime.h>
#include <cuda_fp16.h>
#include <cstdint>
#include <math.h>

#define BB   32
#define SEQ  577
#define DIM  768
#define QKVD 2304
#define ROWS (BB * SEQ)      // 18464
#define SPAD 640

// ---------------- scratch ----------------
__device__ __half g_xh  [(size_t)ROWS * DIM];
__device__ __half g_wqh [(size_t)QKVD * DIM];
__device__ __half g_wph [(size_t)DIM * DIM];
__device__ __half g_qkvh[(size_t)ROWS * QKVD];
__device__ float  g_s   [(size_t)BB * SEQ * SPAD];
__device__ __half g_p   [(size_t)BB * SEQ * SPAD];
__device__ __half g_vt  [(size_t)BB * DIM * SPAD];
__device__ __half g_yt  [(size_t)BB * DIM * SEQ];

// ---------------- helpers ----------------
__device__ __forceinline__ uint32_t smem_u32(const void* p) {
    uint32_t a;
    asm("{ .reg .u64 t; cvta.to.shared.u64 t, %1; cvt.u32.u64 %0, t; }"
        : "=r"(a) : "l"(p));
    return a;
}
__device__ __forceinline__ void cpa16(uint32_t dst, const __half* src, bool ok) {
    int sz = ok ? 16 : 0;
    asm volatile("cp.async.cg.shared.global [%0], [%1], 16, %2;"
                 :: "r"(dst), "l"(src), "r"(sz));
}
__device__ __forceinline__ void ldsm4(uint32_t a, uint32_t* r) {
    asm volatile("ldmatrix.sync.aligned.m8n8.x4.shared.b16 {%0,%1,%2,%3}, [%4];"
                 : "=r"(r[0]), "=r"(r[1]), "=r"(r[2]), "=r"(r[3]) : "r"(a));
}
__device__ __forceinline__ void mma16(float* d, const uint32_t* a, const uint32_t* b) {
    asm volatile(
        "mma.sync.aligned.m16n8k16.row.col.f32.f16.f16.f32 "
        "{%0,%1,%2,%3}, {%4,%5,%6,%7}, {%8,%9}, {%0,%1,%2,%3};"
        : "+f"(d[0]), "+f"(d[1]), "+f"(d[2]), "+f"(d[3])
        : "r"(a[0]), "r"(a[1]), "r"(a[2]), "r"(a[3]), "r"(b[0]), "r"(b[1]));
}

// ---------------- tiling ----------------
#define STAGE_A 16384
#define STAGE_BYTES 32768
#define NSTAGE 3
#define TC_SMEM (NSTAGE * STAGE_BYTES)   // 96KB -> 2 CTAs/SM

__device__ __forceinline__ void fill_stage(
    const __half* __restrict__ A, const __half* __restrict__ B,
    int M, int N, int lda, int ldb, int m0, int n0, int k0,
    uint32_t st, int tid)
{
    const int q = tid & 7;
    const int r0 = tid >> 3;
    const int swq = (q ^ (r0 & 7)) << 4;
#pragma unroll
    for (int p = 0; p < 4; p++) {
        const int r = r0 + p * 32;
        {
            const int gr = m0 + r;
            const bool ok = gr < M;
            cpa16(st + r * 128 + swq, A + (long)(ok ? gr : 0) * lda + k0 + q * 8, ok);
        }
        {
            const int gr = n0 + r;
            const bool ok = gr < N;
            cpa16(st + STAGE_A + r * 128 + swq,
                  B + (long)(ok ? gr : 0) * ldb + k0 + q * 8, ok);
        }
    }
}

// ---------------------------------------------------------------------------
// NT GEMM, fp16 in, fp32 accum. outHalf=0: C float (+bias); 1: C half.
// K % 64 == 0; lda, ldb % 8 == 0. Batched via blockIdx.z.
// Single __syncthreads per K-iteration (leading barrier doubles as both the
// cp.async visibility fence and the buffer-reuse guard).
// ---------------------------------------------------------------------------
__global__ __launch_bounds__(256, 2) void gemm_h(
    const __half* __restrict__ A, const __half* __restrict__ B,
    void* __restrict__ Cv, const float* __restrict__ bias,
    int M, int N, int K, int lda, int ldb, int ldc,
    long sA, long sB, long sC, float alpha, int outHalf)
{
    extern __shared__ char smem[];
    const uint32_t sb = smem_u32(smem);
    const int tid = threadIdx.x;
    const int wid = tid >> 5, lane = tid & 31;
    const int wm = wid & 1, wn = wid >> 1;      // warp tile 64(m) x 32(n)

    const int bz = blockIdx.z;
    A += (long)bz * sA;  B += (long)bz * sB;
    const int m0 = blockIdx.y * 128;
    const int n0 = blockIdx.x * 128;
    const int KT = K >> 6;

    // A ldmatrix.x4 addressing: rows 0-15 of the m16 tile, +16B for upper k8
    const int a_row = lane & 15;
    const int a_co  = lane >> 4;
    // B ldmatrix.x4 addressing for an nt-pair (16 rows):
    //   mats = {nt:k0-7, nt:k8-15, nt+1:k0-7, nt+1:k8-15}
    const int b_rowoff = ((lane >> 4) & 1) * 8 + (lane & 7);
    const int b_co     = (lane >> 3) & 1;

    uint32_t a_off[4], b_off[2];
#pragma unroll
    for (int mt = 0; mt < 4; mt++) {
        const int row = wm * 64 + mt * 16 + a_row;
        a_off[mt] = row * 128 + ((a_co ^ (row & 7)) << 4);
    }
#pragma unroll
    for (int np_ = 0; np_ < 2; np_++) {
        const int row = wn * 32 + np_ * 16 + b_rowoff;
        b_off[np_] = STAGE_A + row * 128 + ((b_co ^ (row & 7)) << 4);
    }

    float acc[4][4][4];
#pragma unroll
    for (int i = 0; i < 4; i++)
#pragma unroll
        for (int j = 0; j < 4; j++)
#pragma unroll
            for (int r = 0; r < 4; r++) acc[i][j][r] = 0.f;

    fill_stage(A, B, M, N, lda, ldb, m0, n0, 0, sb, tid);
    asm volatile("cp.async.commit_group;" ::: "memory");
    if (KT > 1)
        fill_stage(A, B, M, N, lda, ldb, m0, n0, 64, sb + STAGE_BYTES, tid);
    asm volatile("cp.async.commit_group;" ::: "memory");

    for (int kt = 0; kt < KT; kt++) {
        asm volatile("cp.async.wait_group 1;" ::: "memory");
        __syncthreads();

        const int fs = kt + 2;
        if (fs < KT)
            fill_stage(A, B, M, N, lda, ldb, m0, n0, fs * 64,
                       sb + (fs % NSTAGE) * STAGE_BYTES, tid);
        asm volatile("cp.async.commit_group;" ::: "memory");

        const uint32_t st = sb + (kt % NSTAGE) * STAGE_BYTES;

#pragma unroll
        for (int s = 0; s < 4; s++) {           // 4 x K16
            const uint32_t ksw = (uint32_t)(2 * s) << 4;
            uint32_t af[4][4], bf[2][4];
#pragma unroll
            for (int mt = 0; mt < 4; mt++)
                ldsm4(st + (a_off[mt] ^ ksw), af[mt]);
#pragma unroll
            for (int np_ = 0; np_ < 2; np_++)
                ldsm4(st + (b_off[np_] ^ ksw), bf[np_]);
#pragma unroll
            for (int mt = 0; mt < 4; mt++)
#pragma unroll
                for (int nt = 0; nt < 4; nt++)
                    mma16(acc[mt][nt], af[mt], &bf[nt >> 1][(nt & 1) * 2]);
        }
    }

    // epilogue (acc in regs only; no smem reuse -> no barrier needed)
    const int r4 = lane >> 2, cp2 = (lane & 3) * 2;
    if (outHalf) {
        __half* C = (__half*)Cv + (long)bz * sC;
        const bool vec = ((ldc & 1) == 0);
#pragma unroll
        for (int mt = 0; mt < 4; mt++)
#pragma unroll
            for (int half_ = 0; half_ < 2; half_++) {
                const int m = m0 + wm * 64 + mt * 16 + r4 + half_ * 8;
                if (m >= M) continue;
                const long base = (long)m * ldc;
#pragma unroll
                for (int nt = 0; nt < 4; nt++) {
                    const int n = n0 + wn * 32 + nt * 8 + cp2;
                    if (n >= N) continue;
                    const float v0 = acc[mt][nt][half_ * 2 + 0] * alpha;
                    const float v1 = acc[mt][nt][half_ * 2 + 1] * alpha;
                    if (vec && (n + 1 < N)) {
                        *(__half2*)(C + base + n) = __floats2half2_rn(v0, v1);
                    } else {
                        C[base + n] = __float2half_rn(v0);
                        if (n + 1 < N) C[base + n + 1] = __float2half_rn(v1);
                    }
                }
            }
    } else {
        float* C = (float*)Cv + (long)bz * sC;
#pragma unroll
        for (int mt = 0; mt < 4; mt++)
#pragma unroll
            for (int half_ = 0; half_ < 2; half_++) {
                const int m = m0 + wm * 64 + mt * 16 + r4 + half_ * 8;
                if (m >= M) continue;
                const long base = (long)m * ldc;
#pragma unroll
                for (int nt = 0; nt < 4; nt++) {
                    const int n = n0 + wn * 32 + nt * 8 + cp2;
                    if (n >= N) continue;
                    float v0 = acc[mt][nt][half_ * 2 + 0] * alpha;
                    float v1 = acc[mt][nt][half_ * 2 + 1] * alpha;
                    if (bias) {
                        v0 += bias[n];
                        if (n + 1 < N) v1 += bias[n + 1];
                    }
                    if ((ldc & 1) == 0 && (n + 1 < N)) {
                        *(float2*)(C + base + n) = make_float2(v0, v1);
                    } else {
                        C[base + n] = v0;
                        if (n + 1 < N) C[base + n + 1] = v1;
                    }
                }
            }
    }
}

// ---------------- fp32 -> fp16 ----------------
__global__ void f2h_kernel(const float* __restrict__ in, __half* __restrict__ out,
                           long n) {
    const long i = ((long)blockIdx.x * blockDim.x + threadIdx.x) * 4;
    if (i + 3 < n) {
        const float4 v = *(const float4*)(in + i);
        *(__half2*)(out + i)     = __floats2half2_rn(v.x, v.y);
        *(__half2*)(out + i + 2) = __floats2half2_rn(v.z, v.w);
    } else {
        for (long j = i; j < n; j++) out[j] = __float2half_rn(in[j]);
    }
}

// ---------------- softmax: fp32 -> fp16 P (+pad, +token-attn) ----------------
__global__ __launch_bounds__(256) void softmax_kernel(
    const float* __restrict__ S, __half* __restrict__ P, float* __restrict__ tok)
{
    const int row = blockIdx.x;
    const float* p = S + (long)row * SPAD;
    __half* o = P + (long)row * SPAD;
    const int tid = threadIdx.x;
    __shared__ float red[256];

    float v[3];
    float m = -1e30f;
#pragma unroll
    for (int i = 0; i < 3; i++) {
        const int c = tid + i * 256;
        v[i] = (c < SEQ) ? p[c] : -1e30f;
        m = fmaxf(m, v[i]);
    }
    red[tid] = m; __syncthreads();
    for (int s = 128; s > 0; s >>= 1) {
        if (tid < s) red[tid] = fmaxf(red[tid], red[tid + s]);
        __syncthreads();
    }
    m = red[0];
    __syncthreads();

    float sum = 0.f;
#pragma unroll
    for (int i = 0; i < 3; i++) {
        const int c = tid + i * 256;
        if (c < SEQ) { v[i] = __expf(v[i] - m); sum += v[i]; }
    }
    red[tid] = sum; __syncthreads();
    for (int s = 128; s > 0; s >>= 1) {
        if (tid < s) red[tid] += red[tid + s];
        __syncthreads();
    }
    const float inv = 1.0f / red[0];

    const bool tokrow = ((row % SEQ) == 0);
    const int b = row / SEQ;
#pragma unroll
    for (int i = 0; i < 3; i++) {
        const int c = tid + i * 256;
        if (c < SEQ) {
            const float x = v[i] * inv;
            o[c] = __float2half_rn(x);
            if (tokrow && c >= 1) tok[(long)b * (SEQ - 1) + (c - 1)] = x;
        } else if (c < SPAD) {
            o[c] = __float2half_rn(0.f);
        }
    }
}

// V -> Vt[b][c][k], zero pad
__global__ void transpose_v(const __half* __restrict__ qkvh,
                            __half* __restrict__ vt) {
    __shared__ __half t[32][34];
    const int b = blockIdx.z;
    const int k0 = blockIdx.x * 32, c0 = blockIdx.y * 32;
    const int tx = threadIdx.x, ty = threadIdx.y;
#pragma unroll
    for (int i = 0; i < 32; i += 8) {
        const int k = k0 + ty + i, c = c0 + tx;
        __half v = __float2half_rn(0.f);
        if (k < SEQ) v = qkvh[((long)(b * SEQ + k)) * QKVD + 2 * DIM + c];
        t[ty + i][tx] = v;
    }
    __syncthreads();
#pragma unroll
    for (int i = 0; i < 32; i += 8) {
        const int c = c0 + ty + i, k = k0 + tx;
        vt[(long)b * DIM * SPAD + (long)c * SPAD + k] = t[tx][ty + i];
    }
}

// ---------------------------------------------------------------------------
extern "C" void kernel_launch(void* const* d_in, const int* in_sizes, int n_in,
                              void* d_out, int out_size)
{
    const float* x      = (const float*)d_in[0];
    const float* w_qkv  = (const float*)d_in[1];
    const float* w_proj = (const float*)d_in[2];
    const float* b_proj = (const float*)d_in[3];
    float* out = (float*)d_out;
    float* tok = out + (size_t)ROWS * DIM;

    __half *xh, *wqh, *wph, *qkvh, *p, *vt, *yt;
    float *s;
    cudaGetSymbolAddress((void**)&xh,   g_xh);
    cudaGetSymbolAddress((void**)&wqh,  g_wqh);
    cudaGetSymbolAddress((void**)&wph,  g_wph);
    cudaGetSymbolAddress((void**)&qkvh, g_qkvh);
    cudaGetSymbolAddress((void**)&s,    g_s);
    cudaGetSymbolAddress((void**)&p,    g_p);
    cudaGetSymbolAddress((void**)&vt,   g_vt);
    cudaGetSymbolAddress((void**)&yt,   g_yt);

    cudaFuncSetAttribute(gemm_h, cudaFuncAttributeMaxDynamicSharedMemorySize, TC_SMEM);

    const float scale = 1.0f / sqrtf((float)DIM);

    {
        const long nx = (long)ROWS * DIM;
        f2h_kernel<<<(int)((nx / 4 + 255) / 256), 256>>>(x, xh, nx);
        const long nw = (long)QKVD * DIM;
        f2h_kernel<<<(int)((nw / 4 + 255) / 256), 256>>>(w_qkv, wqh, nw);
        const long np = (long)DIM * DIM;
        f2h_kernel<<<(int)((np / 4 + 255) / 256), 256>>>(w_proj, wph, np);
    }

    // 1) QKV (half out)
    gemm_h<<<dim3(QKVD / 128, (ROWS + 127) / 128, 1), 256, TC_SMEM>>>(
        xh, wqh, qkvh, nullptr, ROWS, QKVD, DIM, DIM, DIM, QKVD,
        0, 0, 0, 1.0f, 1);

    // 2) Vt
    transpose_v<<<dim3(SPAD / 32, DIM / 32, BB), dim3(32, 8)>>>(qkvh, vt);

    // 3) S = scale * Q K^T (float out)
    gemm_h<<<dim3((SEQ + 127) / 128, (SEQ + 127) / 128, BB), 256, TC_SMEM>>>(
        qkvh, qkvh + DIM, s, nullptr, SEQ, SEQ, DIM, QKVD, QKVD, SPAD,
        (long)SEQ * QKVD, (long)SEQ * QKVD, (long)SEQ * SPAD, scale, 0);

    // 4) softmax -> fp16 P
    softmax_kernel<<<ROWS, 256>>>(s, p, tok);

    // 5) yt = Vt @ P^T (half out, transposed layout direct)
    gemm_h<<<dim3((SEQ + 127) / 128, DIM / 128, BB), 256, TC_SMEM>>>(
        vt, p, yt, nullptr, DIM, SEQ, SPAD, SPAD, SPAD, SEQ,
        (long)DIM * SPAD, (long)SEQ * SPAD, (long)DIM * SEQ, 1.0f, 1);

    // 6) out = Y2 @ Wproj^T + bias (float out)
    gemm_h<<<dim3(DIM / 128, (ROWS + 127) / 128, 1), 256, TC_SMEM>>>(
        yt, wph, out, b_proj, ROWS, DIM, DIM, DIM, DIM, DIM,
        0, 0, 0, 1.0f, 0);
}

// round 8
// speedup vs baseline: 6.7633x; 1.0140x over previous
#include <cuda_runtime.h>
#include <cuda_fp16.h>
#include <cstdint>
#include <math.h>

#define BB   32
#define SEQ  577
#define DIM  768
#define QKVD 2304
#define ROWS (BB * SEQ)      // 18464
#define SPAD 640

// ---------------- scratch ----------------
__device__ __half g_xh  [(size_t)ROWS * DIM];
__device__ __half g_wqh [(size_t)QKVD * DIM];
__device__ __half g_wph [(size_t)DIM * DIM];
__device__ __half g_qkvh[(size_t)ROWS * QKVD];
__device__ float  g_s   [(size_t)BB * SEQ * SPAD];
__device__ __half g_p   [(size_t)BB * SEQ * SPAD];
__device__ __half g_vt  [(size_t)BB * DIM * SPAD];
__device__ __half g_yt  [(size_t)BB * DIM * SEQ];

// ---------------- helpers ----------------
__device__ __forceinline__ uint32_t smem_u32(const void* p) {
    uint32_t a;
    asm("{ .reg .u64 t; cvta.to.shared.u64 t, %1; cvt.u32.u64 %0, t; }"
        : "=r"(a) : "l"(p));
    return a;
}
__device__ __forceinline__ void cpa16(uint32_t dst, const __half* src, bool ok) {
    int sz = ok ? 16 : 0;
    asm volatile("cp.async.cg.shared.global [%0], [%1], 16, %2;"
                 :: "r"(dst), "l"(src), "r"(sz));
}
__device__ __forceinline__ void ldsm4(uint32_t a, uint32_t* r) {
    asm volatile("ldmatrix.sync.aligned.m8n8.x4.shared.b16 {%0,%1,%2,%3}, [%4];"
                 : "=r"(r[0]), "=r"(r[1]), "=r"(r[2]), "=r"(r[3]) : "r"(a));
}
__device__ __forceinline__ void mma16(float* d, const uint32_t* a, const uint32_t* b) {
    asm volatile(
        "mma.sync.aligned.m16n8k16.row.col.f32.f16.f16.f32 "
        "{%0,%1,%2,%3}, {%4,%5,%6,%7}, {%8,%9}, {%0,%1,%2,%3};"
        : "+f"(d[0]), "+f"(d[1]), "+f"(d[2]), "+f"(d[3])
        : "r"(a[0]), "r"(a[1]), "r"(a[2]), "r"(a[3]), "r"(b[0]), "r"(b[1]));
}

// ---------------- tiling ----------------
#define STAGE_A 16384
#define STAGE_BYTES 32768
#define NSTAGE 3
#define TC_SMEM (NSTAGE * STAGE_BYTES)   // 96KB -> 2 CTAs/SM

__device__ __forceinline__ void fill_stage(
    const __half* __restrict__ A, const __half* __restrict__ B,
    int M, int N, int lda, int ldb, int m0, int n0, int k0,
    uint32_t st, int tid)
{
    const int q = tid & 7;
    const int r0 = tid >> 3;
    const int swq = (q ^ (r0 & 7)) << 4;
#pragma unroll
    for (int p = 0; p < 4; p++) {
        const int r = r0 + p * 32;
        {
            const int gr = m0 + r;
            const bool ok = gr < M;
            cpa16(st + r * 128 + swq, A + (long)(ok ? gr : 0) * lda + k0 + q * 8, ok);
        }
        {
            const int gr = n0 + r;
            const bool ok = gr < N;
            cpa16(st + STAGE_A + r * 128 + swq,
                  B + (long)(ok ? gr : 0) * ldb + k0 + q * 8, ok);
        }
    }
}

// ---------------------------------------------------------------------------
// NT GEMM, fp16 in, fp32 accum. outHalf=0: C float (+bias); 1: C half.
// fuseV: columns n >= 1536 are written transposed into vtOut[b][n-1536][m%SEQ]
// instead of C (QKV fusion). K % 64 == 0; lda, ldb % 8 == 0.
// ---------------------------------------------------------------------------
__global__ __launch_bounds__(256, 2) void gemm_h(
    const __half* __restrict__ A, const __half* __restrict__ B,
    void* __restrict__ Cv, const float* __restrict__ bias,
    int M, int N, int K, int lda, int ldb, int ldc,
    long sA, long sB, long sC, float alpha, int outHalf,
    int fuseV, __half* __restrict__ vtOut)
{
    extern __shared__ char smem[];
    const uint32_t sb = smem_u32(smem);
    const int tid = threadIdx.x;
    const int wid = tid >> 5, lane = tid & 31;
    const int wm = wid & 1, wn = wid >> 1;      // warp tile 64(m) x 32(n)

    const int bz = blockIdx.z;
    A += (long)bz * sA;  B += (long)bz * sB;
    const int m0 = blockIdx.y * 128;
    const int n0 = blockIdx.x * 128;
    const int KT = K >> 6;

    const int a_row = lane & 15;
    const int a_co  = lane >> 4;
    const int b_rowoff = ((lane >> 4) & 1) * 8 + (lane & 7);
    const int b_co     = (lane >> 3) & 1;

    uint32_t a_off[4], b_off[2];
#pragma unroll
    for (int mt = 0; mt < 4; mt++) {
        const int row = wm * 64 + mt * 16 + a_row;
        a_off[mt] = row * 128 + ((a_co ^ (row & 7)) << 4);
    }
#pragma unroll
    for (int np_ = 0; np_ < 2; np_++) {
        const int row = wn * 32 + np_ * 16 + b_rowoff;
        b_off[np_] = STAGE_A + row * 128 + ((b_co ^ (row & 7)) << 4);
    }

    float acc[4][4][4];
#pragma unroll
    for (int i = 0; i < 4; i++)
#pragma unroll
        for (int j = 0; j < 4; j++)
#pragma unroll
            for (int r = 0; r < 4; r++) acc[i][j][r] = 0.f;

    fill_stage(A, B, M, N, lda, ldb, m0, n0, 0, sb, tid);
    asm volatile("cp.async.commit_group;" ::: "memory");
    if (KT > 1)
        fill_stage(A, B, M, N, lda, ldb, m0, n0, 64, sb + STAGE_BYTES, tid);
    asm volatile("cp.async.commit_group;" ::: "memory");

    for (int kt = 0; kt < KT; kt++) {
        asm volatile("cp.async.wait_group 1;" ::: "memory");
        __syncthreads();

        const uint32_t st = sb + (kt % NSTAGE) * STAGE_BYTES;

        // s = 0: start MMAs immediately after the barrier (refill comes after)
        {
            uint32_t af[4][4], bf[2][4];
#pragma unroll
            for (int mt = 0; mt < 4; mt++) ldsm4(st + a_off[mt], af[mt]);
#pragma unroll
            for (int np_ = 0; np_ < 2; np_++) ldsm4(st + b_off[np_], bf[np_]);
#pragma unroll
            for (int mt = 0; mt < 4; mt++)
#pragma unroll
                for (int nt = 0; nt < 4; nt++)
                    mma16(acc[mt][nt], af[mt], &bf[nt >> 1][(nt & 1) * 2]);
        }

        // refill stage kt+2 while s=1..3 compute
        const int fs = kt + 2;
        if (fs < KT)
            fill_stage(A, B, M, N, lda, ldb, m0, n0, fs * 64,
                       sb + (fs % NSTAGE) * STAGE_BYTES, tid);
        asm volatile("cp.async.commit_group;" ::: "memory");

#pragma unroll
        for (int s = 1; s < 4; s++) {
            const uint32_t ksw = (uint32_t)(2 * s) << 4;
            uint32_t af[4][4], bf[2][4];
#pragma unroll
            for (int mt = 0; mt < 4; mt++)
                ldsm4(st + (a_off[mt] ^ ksw), af[mt]);
#pragma unroll
            for (int np_ = 0; np_ < 2; np_++)
                ldsm4(st + (b_off[np_] ^ ksw), bf[np_]);
#pragma unroll
            for (int mt = 0; mt < 4; mt++)
#pragma unroll
                for (int nt = 0; nt < 4; nt++)
                    mma16(acc[mt][nt], af[mt], &bf[nt >> 1][(nt & 1) * 2]);
        }
    }

    // epilogue
    const int r4 = lane >> 2, cp2 = (lane & 3) * 2;
    if (outHalf) {
        __half* C = (__half*)Cv + (long)bz * sC;
        const bool vec = ((ldc & 1) == 0);
#pragma unroll
        for (int mt = 0; mt < 4; mt++)
#pragma unroll
            for (int half_ = 0; half_ < 2; half_++) {
                const int m = m0 + wm * 64 + mt * 16 + r4 + half_ * 8;
                if (m >= M) continue;
                const long base = (long)m * ldc;
#pragma unroll
                for (int nt = 0; nt < 4; nt++) {
                    const int n = n0 + wn * 32 + nt * 8 + cp2;
                    if (n >= N) continue;
                    const float v0 = acc[mt][nt][half_ * 2 + 0] * alpha;
                    const float v1 = acc[mt][nt][half_ * 2 + 1] * alpha;
                    if (fuseV && n >= 1536) {
                        // vt[b][c][k] = value, c = n-1536, k = m % SEQ
                        const int b = m / SEQ;
                        const int kk = m - b * SEQ;
                        __half* dst = vtOut + (long)b * DIM * SPAD
                                            + (long)(n - 1536) * SPAD + kk;
                        dst[0]    = __float2half_rn(v0);
                        dst[SPAD] = __float2half_rn(v1);
                    } else if (vec && (n + 1 < N)) {
                        *(__half2*)(C + base + n) = __floats2half2_rn(v0, v1);
                    } else {
                        C[base + n] = __float2half_rn(v0);
                        if (n + 1 < N) C[base + n + 1] = __float2half_rn(v1);
                    }
                }
            }
    } else {
        float* C = (float*)Cv + (long)bz * sC;
#pragma unroll
        for (int mt = 0; mt < 4; mt++)
#pragma unroll
            for (int half_ = 0; half_ < 2; half_++) {
                const int m = m0 + wm * 64 + mt * 16 + r4 + half_ * 8;
                if (m >= M) continue;
                const long base = (long)m * ldc;
#pragma unroll
                for (int nt = 0; nt < 4; nt++) {
                    const int n = n0 + wn * 32 + nt * 8 + cp2;
                    if (n >= N) continue;
                    float v0 = acc[mt][nt][half_ * 2 + 0] * alpha;
                    float v1 = acc[mt][nt][half_ * 2 + 1] * alpha;
                    if (bias) {
                        v0 += bias[n];
                        if (n + 1 < N) v1 += bias[n + 1];
                    }
                    if ((ldc & 1) == 0 && (n + 1 < N)) {
                        *(float2*)(C + base + n) = make_float2(v0, v1);
                    } else {
                        C[base + n] = v0;
                        if (n + 1 < N) C[base + n + 1] = v1;
                    }
                }
            }
    }
}

// ---------------- fp32 -> fp16 ----------------
__global__ void f2h_kernel(const float* __restrict__ in, __half* __restrict__ out,
                           long n) {
    const long i = ((long)blockIdx.x * blockDim.x + threadIdx.x) * 4;
    if (i + 3 < n) {
        const float4 v = *(const float4*)(in + i);
        *(__half2*)(out + i)     = __floats2half2_rn(v.x, v.y);
        *(__half2*)(out + i + 2) = __floats2half2_rn(v.z, v.w);
    } else {
        for (long j = i; j < n; j++) out[j] = __float2half_rn(in[j]);
    }
}

// ---------------- zero the Vt K-pad rows (k in [SEQ, SPAD)) ----------------
__global__ void zero_vt_pad(__half* __restrict__ vt) {
    const int i = blockIdx.x * blockDim.x + threadIdx.x;
    const int PADW = SPAD - SEQ;                  // 63
    const int total = BB * DIM * PADW;
    if (i >= total) return;
    const int b = i / (DIM * PADW);
    const int r = i - b * (DIM * PADW);
    const int c = r / PADW;
    const int j = r - c * PADW;
    vt[(long)b * DIM * SPAD + (long)c * SPAD + SEQ + j] = __float2half_rn(0.f);
}

// ---------------- softmax: fp32 -> fp16 P (+pad, +token-attn) ----------------
__global__ __launch_bounds__(256) void softmax_kernel(
    const float* __restrict__ S, __half* __restrict__ P, float* __restrict__ tok)
{
    const int row = blockIdx.x;
    const float* p = S + (long)row * SPAD;
    __half* o = P + (long)row * SPAD;
    const int tid = threadIdx.x;
    const int lane = tid & 31, wid = tid >> 5;
    __shared__ float red[8];

    float v[3];
    float m = -1e30f;
#pragma unroll
    for (int i = 0; i < 3; i++) {
        const int c = tid + i * 256;
        v[i] = (c < SEQ) ? p[c] : -1e30f;
        m = fmaxf(m, v[i]);
    }
#pragma unroll
    for (int off = 16; off > 0; off >>= 1)
        m = fmaxf(m, __shfl_xor_sync(0xFFFFFFFFu, m, off));
    if (lane == 0) red[wid] = m;
    __syncthreads();
    m = red[0];
#pragma unroll
    for (int i = 1; i < 8; i++) m = fmaxf(m, red[i]);
    __syncthreads();

    float sum = 0.f;
#pragma unroll
    for (int i = 0; i < 3; i++) {
        const int c = tid + i * 256;
        if (c < SEQ) { v[i] = __expf(v[i] - m); sum += v[i]; }
    }
#pragma unroll
    for (int off = 16; off > 0; off >>= 1)
        sum += __shfl_xor_sync(0xFFFFFFFFu, sum, off);
    if (lane == 0) red[wid] = sum;
    __syncthreads();
    sum = red[0];
#pragma unroll
    for (int i = 1; i < 8; i++) sum += red[i];
    const float inv = 1.0f / sum;

    const bool tokrow = ((row % SEQ) == 0);
    const int b = row / SEQ;
#pragma unroll
    for (int i = 0; i < 3; i++) {
        const int c = tid + i * 256;
        if (c < SEQ) {
            const float x = v[i] * inv;
            o[c] = __float2half_rn(x);
            if (tokrow && c >= 1) tok[(long)b * (SEQ - 1) + (c - 1)] = x;
        } else if (c < SPAD) {
            o[c] = __float2half_rn(0.f);
        }
    }
}

// ---------------------------------------------------------------------------
extern "C" void kernel_launch(void* const* d_in, const int* in_sizes, int n_in,
                              void* d_out, int out_size)
{
    const float* x      = (const float*)d_in[0];
    const float* w_qkv  = (const float*)d_in[1];
    const float* w_proj = (const float*)d_in[2];
    const float* b_proj = (const float*)d_in[3];
    float* out = (float*)d_out;
    float* tok = out + (size_t)ROWS * DIM;

    __half *xh, *wqh, *wph, *qkvh, *p, *vt, *yt;
    float *s;
    cudaGetSymbolAddress((void**)&xh,   g_xh);
    cudaGetSymbolAddress((void**)&wqh,  g_wqh);
    cudaGetSymbolAddress((void**)&wph,  g_wph);
    cudaGetSymbolAddress((void**)&qkvh, g_qkvh);
    cudaGetSymbolAddress((void**)&s,    g_s);
    cudaGetSymbolAddress((void**)&p,    g_p);
    cudaGetSymbolAddress((void**)&vt,   g_vt);
    cudaGetSymbolAddress((void**)&yt,   g_yt);

    cudaFuncSetAttribute(gemm_h, cudaFuncAttributeMaxDynamicSharedMemorySize, TC_SMEM);

    const float scale = 1.0f / sqrtf((float)DIM);

    {
        const long nx = (long)ROWS * DIM;
        f2h_kernel<<<(int)((nx / 4 + 255) / 256), 256>>>(x, xh, nx);
        const long nw = (long)QKVD * DIM;
        f2h_kernel<<<(int)((nw / 4 + 255) / 256), 256>>>(w_qkv, wqh, nw);
        const long np = (long)DIM * DIM;
        f2h_kernel<<<(int)((np / 4 + 255) / 256), 256>>>(w_proj, wph, np);
        zero_vt_pad<<<(BB * DIM * (SPAD - SEQ) + 255) / 256, 256>>>(vt);
    }

    // 1) QKV (half out; V columns written transposed into vt)
    gemm_h<<<dim3(QKVD / 128, (ROWS + 127) / 128, 1), 256, TC_SMEM>>>(
        xh, wqh, qkvh, nullptr, ROWS, QKVD, DIM, DIM, DIM, QKVD,
        0, 0, 0, 1.0f, 1, 1, vt);

    // 2) S = scale * Q K^T (float out)
    gemm_h<<<dim3((SEQ + 127) / 128, (SEQ + 127) / 128, BB), 256, TC_SMEM>>>(
        qkvh, qkvh + DIM, s, nullptr, SEQ, SEQ, DIM, QKVD, QKVD, SPAD,
        (long)SEQ * QKVD, (long)SEQ * QKVD, (long)SEQ * SPAD, scale, 0, 0, nullptr);

    // 3) softmax -> fp16 P
    softmax_kernel<<<ROWS, 256>>>(s, p, tok);

    // 4) yt = Vt @ P^T (half out, transposed layout direct)
    gemm_h<<<dim3((SEQ + 127) / 128, DIM / 128, BB), 256, TC_SMEM>>>(
        vt, p, yt, nullptr, DIM, SEQ, SPAD, SPAD, SPAD, SEQ,
        (long)DIM * SPAD, (long)SEQ * SPAD, (long)DIM * SEQ, 1.0f, 1, 0, nullptr);

    // 5) out = Y2 @ Wproj^T + bias (float out)
    gemm_h<<<dim3(DIM / 128, (ROWS + 127) / 128, 1), 256, TC_SMEM>>>(
        yt, wph, out, b_proj, ROWS, DIM, DIM, DIM, DIM, DIM,
        0, 0, 0, 1.0f, 0, 0, nullptr);
}

// round 9
// speedup vs baseline: 6.9646x; 1.0298x over previous
#include <cuda_runtime.h>
#include <cuda_fp16.h>
#include <cstdint>
#include <math.h>

#define BB   32
#define SEQ  577
#define DIM  768
#define QKVD 2304
#define ROWS (BB * SEQ)      // 18464
#define SPAD 640

// ---------------- scratch ----------------
__device__ __half g_xh  [(size_t)ROWS * DIM];
__device__ __half g_wqh [(size_t)QKVD * DIM];
__device__ __half g_wph [(size_t)DIM * DIM];
__device__ __half g_qkvh[(size_t)ROWS * QKVD];
__device__ float  g_s   [(size_t)BB * SEQ * SPAD];
__device__ __half g_p   [(size_t)BB * SEQ * SPAD];
__device__ __half g_vt  [(size_t)BB * DIM * SPAD];
__device__ __half g_yt  [(size_t)BB * DIM * SEQ];

// ---------------- helpers ----------------
__device__ __forceinline__ uint32_t smem_u32(const void* p) {
    uint32_t a;
    asm("{ .reg .u64 t; cvta.to.shared.u64 t, %1; cvt.u32.u64 %0, t; }"
        : "=r"(a) : "l"(p));
    return a;
}
__device__ __forceinline__ void cpa16(uint32_t dst, const __half* src, bool ok) {
    int sz = ok ? 16 : 0;
    asm volatile("cp.async.cg.shared.global [%0], [%1], 16, %2;"
                 :: "r"(dst), "l"(src), "r"(sz));
}
__device__ __forceinline__ void ldsm4(uint32_t a, uint32_t* r) {
    asm volatile("ldmatrix.sync.aligned.m8n8.x4.shared.b16 {%0,%1,%2,%3}, [%4];"
                 : "=r"(r[0]), "=r"(r[1]), "=r"(r[2]), "=r"(r[3]) : "r"(a));
}
__device__ __forceinline__ void mma16(float* d, const uint32_t* a, const uint32_t* b) {
    asm volatile(
        "mma.sync.aligned.m16n8k16.row.col.f32.f16.f16.f32 "
        "{%0,%1,%2,%3}, {%4,%5,%6,%7}, {%8,%9}, {%0,%1,%2,%3};"
        : "+f"(d[0]), "+f"(d[1]), "+f"(d[2]), "+f"(d[3])
        : "r"(a[0]), "r"(a[1]), "r"(a[2]), "r"(a[3]), "r"(b[0]), "r"(b[1]));
}

// ---------------- tiling ----------------
#define STAGE_A 16384
#define STAGE_BYTES 32768
#define NSTAGE 3
#define TC_SMEM (NSTAGE * STAGE_BYTES)   // 96KB -> 2 CTAs/SM

__device__ __forceinline__ void fill_stage(
    const __half* __restrict__ A, const __half* __restrict__ B,
    int M, int N, int lda, int ldb, int m0, int n0, int k0,
    uint32_t st, int tid)
{
    const int q = tid & 7;
    const int r0 = tid >> 3;
    const int swq = (q ^ (r0 & 7)) << 4;
#pragma unroll
    for (int p = 0; p < 4; p++) {
        const int r = r0 + p * 32;
        {
            const int gr = m0 + r;
            const bool ok = gr < M;
            cpa16(st + r * 128 + swq, A + (long)(ok ? gr : 0) * lda + k0 + q * 8, ok);
        }
        {
            const int gr = n0 + r;
            const bool ok = gr < N;
            cpa16(st + STAGE_A + r * 128 + swq,
                  B + (long)(ok ? gr : 0) * ldb + k0 + q * 8, ok);
        }
    }
}

// ---------------------------------------------------------------------------
// NT GEMM, fp16 in, fp32 accum. outHalf=0: C float (+bias); 1: C half.
// fuseV: columns n >= 1536 are written transposed into vtOut.
// ---------------------------------------------------------------------------
__global__ __launch_bounds__(256, 2) void gemm_h(
    const __half* __restrict__ A, const __half* __restrict__ B,
    void* __restrict__ Cv, const float* __restrict__ bias,
    int M, int N, int K, int lda, int ldb, int ldc,
    long sA, long sB, long sC, float alpha, int outHalf,
    int fuseV, __half* __restrict__ vtOut)
{
    extern __shared__ char smem[];
    const uint32_t sb = smem_u32(smem);
    const int tid = threadIdx.x;
    const int wid = tid >> 5, lane = tid & 31;
    const int wm = wid & 1, wn = wid >> 1;      // warp tile 64(m) x 32(n)

    const int bz = blockIdx.z;
    A += (long)bz * sA;  B += (long)bz * sB;
    const int m0 = blockIdx.y * 128;
    const int n0 = blockIdx.x * 128;
    const int KT = K >> 6;

    // Lean addressing: tile-row offsets are multiples of 8, so the swizzle
    // nibble depends only on the lane. One base register per operand:
    //   addr(mt, s) = st + (base ^ (2s<<4)) + mt*2048
    const int a_row = lane & 15;
    const int a_co  = lane >> 4;
    const uint32_t a_base = (uint32_t)((wm * 64 + a_row) * 128 +
                                       ((a_co ^ (a_row & 7)) << 4));
    const int b_rowoff = ((lane >> 4) & 1) * 8 + (lane & 7);
    const int b_co     = (lane >> 3) & 1;
    const uint32_t b_base = (uint32_t)(STAGE_A + (wn * 32 + b_rowoff) * 128 +
                                       ((b_co ^ (b_rowoff & 7)) << 4));

    float acc[4][4][4];
#pragma unroll
    for (int i = 0; i < 4; i++)
#pragma unroll
        for (int j = 0; j < 4; j++)
#pragma unroll
            for (int r = 0; r < 4; r++) acc[i][j][r] = 0.f;

    fill_stage(A, B, M, N, lda, ldb, m0, n0, 0, sb, tid);
    asm volatile("cp.async.commit_group;" ::: "memory");
    if (KT > 1)
        fill_stage(A, B, M, N, lda, ldb, m0, n0, 64, sb + STAGE_BYTES, tid);
    asm volatile("cp.async.commit_group;" ::: "memory");

    for (int kt = 0; kt < KT; kt++) {
        asm volatile("cp.async.wait_group 1;" ::: "memory");
        __syncthreads();

        const uint32_t st = sb + (kt % NSTAGE) * STAGE_BYTES;

        // s = 0 (B first, then A; first mma depends only on af[0])
        {
            const uint32_t ba = st + a_base, bb = st + b_base;
            uint32_t bf[2][4], af[4][4];
            ldsm4(bb,        bf[0]);
            ldsm4(bb + 2048, bf[1]);
#pragma unroll
            for (int mt = 0; mt < 4; mt++) ldsm4(ba + mt * 2048, af[mt]);
#pragma unroll
            for (int mt = 0; mt < 4; mt++)
#pragma unroll
                for (int nt = 0; nt < 4; nt++)
                    mma16(acc[mt][nt], af[mt], &bf[nt >> 1][(nt & 1) * 2]);
        }

        // refill stage kt+2 while s=1..3 compute
        const int fs = kt + 2;
        if (fs < KT)
            fill_stage(A, B, M, N, lda, ldb, m0, n0, fs * 64,
                       sb + (fs % NSTAGE) * STAGE_BYTES, tid);
        asm volatile("cp.async.commit_group;" ::: "memory");

#pragma unroll
        for (int s = 1; s < 4; s++) {
            const uint32_t ksw = (uint32_t)(2 * s) << 4;
            const uint32_t ba = st + (a_base ^ ksw);
            const uint32_t bb = st + (b_base ^ ksw);
            uint32_t bf[2][4], af[4][4];
            ldsm4(bb,        bf[0]);
            ldsm4(bb + 2048, bf[1]);
#pragma unroll
            for (int mt = 0; mt < 4; mt++) ldsm4(ba + mt * 2048, af[mt]);
#pragma unroll
            for (int mt = 0; mt < 4; mt++)
#pragma unroll
                for (int nt = 0; nt < 4; nt++)
                    mma16(acc[mt][nt], af[mt], &bf[nt >> 1][(nt & 1) * 2]);
        }
    }

    // epilogue
    const int r4 = lane >> 2, cp2 = (lane & 3) * 2;
    if (outHalf) {
        __half* C = (__half*)Cv + (long)bz * sC;
        const bool vec = ((ldc & 1) == 0);
#pragma unroll
        for (int mt = 0; mt < 4; mt++)
#pragma unroll
            for (int half_ = 0; half_ < 2; half_++) {
                const int m = m0 + wm * 64 + mt * 16 + r4 + half_ * 8;
                if (m >= M) continue;
                const long base = (long)m * ldc;
#pragma unroll
                for (int nt = 0; nt < 4; nt++) {
                    const int n = n0 + wn * 32 + nt * 8 + cp2;
                    if (n >= N) continue;
                    const float v0 = acc[mt][nt][half_ * 2 + 0] * alpha;
                    const float v1 = acc[mt][nt][half_ * 2 + 1] * alpha;
                    if (fuseV && n >= 1536) {
                        const int b = m / SEQ;
                        const int kk = m - b * SEQ;
                        __half* dst = vtOut + (long)b * DIM * SPAD
                                            + (long)(n - 1536) * SPAD + kk;
                        dst[0]    = __float2half_rn(v0);
                        dst[SPAD] = __float2half_rn(v1);
                    } else if (vec && (n + 1 < N)) {
                        *(__half2*)(C + base + n) = __floats2half2_rn(v0, v1);
                    } else {
                        C[base + n] = __float2half_rn(v0);
                        if (n + 1 < N) C[base + n + 1] = __float2half_rn(v1);
                    }
                }
            }
    } else {
        float* C = (float*)Cv + (long)bz * sC;
#pragma unroll
        for (int mt = 0; mt < 4; mt++)
#pragma unroll
            for (int half_ = 0; half_ < 2; half_++) {
                const int m = m0 + wm * 64 + mt * 16 + r4 + half_ * 8;
                if (m >= M) continue;
                const long base = (long)m * ldc;
#pragma unroll
                for (int nt = 0; nt < 4; nt++) {
                    const int n = n0 + wn * 32 + nt * 8 + cp2;
                    if (n >= N) continue;
                    float v0 = acc[mt][nt][half_ * 2 + 0] * alpha;
                    float v1 = acc[mt][nt][half_ * 2 + 1] * alpha;
                    if (bias) {
                        v0 += bias[n];
                        if (n + 1 < N) v1 += bias[n + 1];
                    }
                    if ((ldc & 1) == 0 && (n + 1 < N)) {
                        *(float2*)(C + base + n) = make_float2(v0, v1);
                    } else {
                        C[base + n] = v0;
                        if (n + 1 < N) C[base + n + 1] = v1;
                    }
                }
            }
    }
}

// ---------------- fp32 -> fp16 ----------------
__global__ void f2h_kernel(const float* __restrict__ in, __half* __restrict__ out,
                           long n) {
    const long i = ((long)blockIdx.x * blockDim.x + threadIdx.x) * 4;
    if (i + 3 < n) {
        const float4 v = *(const float4*)(in + i);
        *(__half2*)(out + i)     = __floats2half2_rn(v.x, v.y);
        *(__half2*)(out + i + 2) = __floats2half2_rn(v.z, v.w);
    } else {
        for (long j = i; j < n; j++) out[j] = __float2half_rn(in[j]);
    }
}

// ---------------- zero Vt pad rows k in [576, 640): float4-vectorized -------
// (k=576 is real data but the QKV GEMM epilogue writes it AFTER this kernel.)
__global__ void zero_vt_pad(__half* __restrict__ vt) {
    const int i = blockIdx.x * blockDim.x + threadIdx.x;   // 8 halves each
    const int PADW = 64;                                    // halves per row
    const int total = BB * DIM * (PADW / 8);
    if (i >= total) return;
    const int rowsPer = PADW / 8;                           // 8 float4 per row
    const int rc = i / rowsPer;                             // which (b,c)
    const int j = i - rc * rowsPer;
    __half* dst = vt + (long)rc * SPAD + 576 + j * 8;
    *(float4*)dst = make_float4(0.f, 0.f, 0.f, 0.f);
}

// ---------------- softmax: fp32 -> fp16 P (+pad, +token-attn) ----------------
__global__ __launch_bounds__(256) void softmax_kernel(
    const float* __restrict__ S, __half* __restrict__ P, float* __restrict__ tok)
{
    const int row = blockIdx.x;
    const float* p = S + (long)row * SPAD;
    __half* o = P + (long)row * SPAD;
    const int tid = threadIdx.x;
    const int lane = tid & 31, wid = tid >> 5;
    __shared__ float red[8];

    float v[3];
    float m = -1e30f;
#pragma unroll
    for (int i = 0; i < 3; i++) {
        const int c = tid + i * 256;
        v[i] = (c < SEQ) ? p[c] : -1e30f;
        m = fmaxf(m, v[i]);
    }
#pragma unroll
    for (int off = 16; off > 0; off >>= 1)
        m = fmaxf(m, __shfl_xor_sync(0xFFFFFFFFu, m, off));
    if (lane == 0) red[wid] = m;
    __syncthreads();
    m = red[0];
#pragma unroll
    for (int i = 1; i < 8; i++) m = fmaxf(m, red[i]);
    __syncthreads();

    float sum = 0.f;
#pragma unroll
    for (int i = 0; i < 3; i++) {
        const int c = tid + i * 256;
        if (c < SEQ) { v[i] = __expf(v[i] - m); sum += v[i]; }
    }
#pragma unroll
    for (int off = 16; off > 0; off >>= 1)
        sum += __shfl_xor_sync(0xFFFFFFFFu, sum, off);
    if (lane == 0) red[wid] = sum;
    __syncthreads();
    sum = red[0];
#pragma unroll
    for (int i = 1; i < 8; i++) sum += red[i];
    const float inv = 1.0f / sum;

    const bool tokrow = ((row % SEQ) == 0);
    const int b = row / SEQ;
#pragma unroll
    for (int i = 0; i < 3; i++) {
        const int c = tid + i * 256;
        if (c < SEQ) {
            const float x = v[i] * inv;
            o[c] = __float2half_rn(x);
            if (tokrow && c >= 1) tok[(long)b * (SEQ - 1) + (c - 1)] = x;
        } else if (c < SPAD) {
            o[c] = __float2half_rn(0.f);
        }
    }
}

// ---------------------------------------------------------------------------
extern "C" void kernel_launch(void* const* d_in, const int* in_sizes, int n_in,
                              void* d_out, int out_size)
{
    const float* x      = (const float*)d_in[0];
    const float* w_qkv  = (const float*)d_in[1];
    const float* w_proj = (const float*)d_in[2];
    const float* b_proj = (const float*)d_in[3];
    float* out = (float*)d_out;
    float* tok = out + (size_t)ROWS * DIM;

    __half *xh, *wqh, *wph, *qkvh, *p, *vt, *yt;
    float *s;
    cudaGetSymbolAddress((void**)&xh,   g_xh);
    cudaGetSymbolAddress((void**)&wqh,  g_wqh);
    cudaGetSymbolAddress((void**)&wph,  g_wph);
    cudaGetSymbolAddress((void**)&qkvh, g_qkvh);
    cudaGetSymbolAddress((void**)&s,    g_s);
    cudaGetSymbolAddress((void**)&p,    g_p);
    cudaGetSymbolAddress((void**)&vt,   g_vt);
    cudaGetSymbolAddress((void**)&yt,   g_yt);

    cudaFuncSetAttribute(gemm_h, cudaFuncAttributeMaxDynamicSharedMemorySize, TC_SMEM);

    const float scale = 1.0f / sqrtf((float)DIM);

    {
        const long nx = (long)ROWS * DIM;
        f2h_kernel<<<(int)((nx / 4 + 255) / 256), 256>>>(x, xh, nx);
        const long nw = (long)QKVD * DIM;
        f2h_kernel<<<(int)((nw / 4 + 255) / 256), 256>>>(w_qkv, wqh, nw);
        const long np = (long)DIM * DIM;
        f2h_kernel<<<(int)((np / 4 + 255) / 256), 256>>>(w_proj, wph, np);
        zero_vt_pad<<<(BB * DIM * 8 + 255) / 256, 256>>>(vt);
    }

    // 1) QKV (half out; V columns written transposed into vt)
    gemm_h<<<dim3(QKVD / 128, (ROWS + 127) / 128, 1), 256, TC_SMEM>>>(
        xh, wqh, qkvh, nullptr, ROWS, QKVD, DIM, DIM, DIM, QKVD,
        0, 0, 0, 1.0f, 1, 1, vt);

    // 2) S = scale * Q K^T (float out)
    gemm_h<<<dim3((SEQ + 127) / 128, (SEQ + 127) / 128, BB), 256, TC_SMEM>>>(
        qkvh, qkvh + DIM, s, nullptr, SEQ, SEQ, DIM, QKVD, QKVD, SPAD,
        (long)SEQ * QKVD, (long)SEQ * QKVD, (long)SEQ * SPAD, scale, 0, 0, nullptr);

    // 3) softmax -> fp16 P
    softmax_kernel<<<ROWS, 256>>>(s, p, tok);

    // 4) yt = Vt @ P^T (half out, transposed layout direct)
    gemm_h<<<dim3((SEQ + 127) / 128, DIM / 128, BB), 256, TC_SMEM>>>(
        vt, p, yt, nullptr, DIM, SEQ, SPAD, SPAD, SPAD, SEQ,
        (long)DIM * SPAD, (long)SEQ * SPAD, (long)DIM * SEQ, 1.0f, 1, 0, nullptr);

    // 5) out = Y2 @ Wproj^T + bias (float out)
    gemm_h<<<dim3(DIM / 128, (ROWS + 127) / 128, 1), 256, TC_SMEM>>>(
        yt, wph, out, b_proj, ROWS, DIM, DIM, DIM, DIM, DIM,
        0, 0, 0, 1.0f, 0, 0, nullptr);
}

// round 10
// speedup vs baseline: 7.0915x; 1.0182x over previous
#include <cuda_runtime.h>
#include <cuda_fp16.h>
#include <cstdint>
#include <math.h>

#define BB   32
#define SEQ  577
#define DIM  768
#define QKVD 2304
#define ROWS (BB * SEQ)      // 18464
#define SPAD 640

// ---------------- scratch ----------------
__device__ __half g_xh  [(size_t)ROWS * DIM];
__device__ __half g_wqh [(size_t)QKVD * DIM];
__device__ __half g_wph [(size_t)DIM * DIM];
__device__ __half g_qkvh[(size_t)ROWS * QKVD];
__device__ float  g_s   [(size_t)BB * SEQ * SPAD];
__device__ __half g_p   [(size_t)BB * SEQ * SPAD];
__device__ __half g_vt  [(size_t)BB * DIM * SPAD];
__device__ __half g_yt  [(size_t)BB * DIM * SEQ];

// ---------------- helpers ----------------
__device__ __forceinline__ uint32_t smem_u32(const void* p) {
    uint32_t a;
    asm("{ .reg .u64 t; cvta.to.shared.u64 t, %1; cvt.u32.u64 %0, t; }"
        : "=r"(a) : "l"(p));
    return a;
}
__device__ __forceinline__ void cpa16(uint32_t dst, const __half* src, bool ok) {
    int sz = ok ? 16 : 0;
    asm volatile("cp.async.cg.shared.global [%0], [%1], 16, %2;"
                 :: "r"(dst), "l"(src), "r"(sz));
}
__device__ __forceinline__ void ldsm4(uint32_t a, uint32_t* r) {
    asm volatile("ldmatrix.sync.aligned.m8n8.x4.shared.b16 {%0,%1,%2,%3}, [%4];"
                 : "=r"(r[0]), "=r"(r[1]), "=r"(r[2]), "=r"(r[3]) : "r"(a));
}
__device__ __forceinline__ void mma16(float* d, const uint32_t* a, const uint32_t* b) {
    asm volatile(
        "mma.sync.aligned.m16n8k16.row.col.f32.f16.f16.f32 "
        "{%0,%1,%2,%3}, {%4,%5,%6,%7}, {%8,%9}, {%0,%1,%2,%3};"
        : "+f"(d[0]), "+f"(d[1]), "+f"(d[2]), "+f"(d[3])
        : "r"(a[0]), "r"(a[1]), "r"(a[2]), "r"(a[3]), "r"(b[0]), "r"(b[1]));
}

// ---------------- tiling ----------------
#define STAGE_A 16384
#define STAGE_BYTES 32768
#define NSTAGE 3
#define TC_SMEM (NSTAGE * STAGE_BYTES)   // 96KB -> 2 CTAs/SM

__device__ __forceinline__ void fill_stage(
    const __half* __restrict__ A, const __half* __restrict__ B,
    int M, int N, int lda, int ldb, int m0, int n0, int k0,
    uint32_t st, int tid)
{
    const int q = tid & 7;
    const int r0 = tid >> 3;
    const int swq = (q ^ (r0 & 7)) << 4;
#pragma unroll
    for (int p = 0; p < 4; p++) {
        const int r = r0 + p * 32;
        {
            const int gr = m0 + r;
            const bool ok = gr < M;
            cpa16(st + r * 128 + swq, A + (long)(ok ? gr : 0) * lda + k0 + q * 8, ok);
        }
        {
            const int gr = n0 + r;
            const bool ok = gr < N;
            cpa16(st + STAGE_A + r * 128 + swq,
                  B + (long)(ok ? gr : 0) * ldb + k0 + q * 8, ok);
        }
    }
}

// ---------------------------------------------------------------------------
// NT GEMM, fp16 in, fp32 accum. outHalf=0: C float (+bias); 1: C half.
// fuseV: columns n >= 1536 are written transposed into vtOut.
// B fragments double-buffered across the 4 K16 sub-steps (register-neutral:
// A fragments are loaded in mt-pairs).
// ---------------------------------------------------------------------------
__global__ __launch_bounds__(256, 2) void gemm_h(
    const __half* __restrict__ A, const __half* __restrict__ B,
    void* __restrict__ Cv, const float* __restrict__ bias,
    int M, int N, int K, int lda, int ldb, int ldc,
    long sA, long sB, long sC, float alpha, int outHalf,
    int fuseV, __half* __restrict__ vtOut)
{
    extern __shared__ char smem[];
    const uint32_t sb = smem_u32(smem);
    const int tid = threadIdx.x;
    const int wid = tid >> 5, lane = tid & 31;
    const int wm = wid & 1, wn = wid >> 1;      // warp tile 64(m) x 32(n)

    const int bz = blockIdx.z;
    A += (long)bz * sA;  B += (long)bz * sB;
    const int m0 = blockIdx.y * 128;
    const int n0 = blockIdx.x * 128;
    const int KT = K >> 6;

    const int a_row = lane & 15;
    const int a_co  = lane >> 4;
    const uint32_t a_base = (uint32_t)((wm * 64 + a_row) * 128 +
                                       ((a_co ^ (a_row & 7)) << 4));
    const int b_rowoff = ((lane >> 4) & 1) * 8 + (lane & 7);
    const int b_co     = (lane >> 3) & 1;
    const uint32_t b_base = (uint32_t)(STAGE_A + (wn * 32 + b_rowoff) * 128 +
                                       ((b_co ^ (b_rowoff & 7)) << 4));

    float acc[4][4][4];
#pragma unroll
    for (int i = 0; i < 4; i++)
#pragma unroll
        for (int j = 0; j < 4; j++)
#pragma unroll
            for (int r = 0; r < 4; r++) acc[i][j][r] = 0.f;

    fill_stage(A, B, M, N, lda, ldb, m0, n0, 0, sb, tid);
    asm volatile("cp.async.commit_group;" ::: "memory");
    if (KT > 1)
        fill_stage(A, B, M, N, lda, ldb, m0, n0, 64, sb + STAGE_BYTES, tid);
    asm volatile("cp.async.commit_group;" ::: "memory");

    for (int kt = 0; kt < KT; kt++) {
        asm volatile("cp.async.wait_group 1;" ::: "memory");
        __syncthreads();

        const uint32_t st = sb + (kt % NSTAGE) * STAGE_BYTES;

        uint32_t bf[2][2][4];                    // [buf][np][regs]
        ldsm4(st + b_base,        bf[0][0]);
        ldsm4(st + b_base + 2048, bf[0][1]);

#pragma unroll
        for (int s = 0; s < 4; s++) {
            const int cur = s & 1, nxt = cur ^ 1;
            if (s < 3) {                         // prefetch B for s+1
                const uint32_t kswn = (uint32_t)(2 * (s + 1)) << 4;
                const uint32_t bb2 = st + (b_base ^ kswn);
                ldsm4(bb2,        bf[nxt][0]);
                ldsm4(bb2 + 2048, bf[nxt][1]);
            }
            const uint32_t ksw = (uint32_t)(2 * s) << 4;
            const uint32_t ba = st + (a_base ^ ksw);
#pragma unroll
            for (int mtp = 0; mtp < 2; mtp++) {  // A in pairs (8 live regs)
                uint32_t af[2][4];
                ldsm4(ba + (2 * mtp) * 2048,     af[0]);
                ldsm4(ba + (2 * mtp + 1) * 2048, af[1]);
#pragma unroll
                for (int mi = 0; mi < 2; mi++) {
                    const int mt = 2 * mtp + mi;
#pragma unroll
                    for (int nt = 0; nt < 4; nt++)
                        mma16(acc[mt][nt], af[mi], &bf[cur][nt >> 1][(nt & 1) * 2]);
                }
            }
            if (s == 0) {                        // refill while s=1..3 compute
                const int fs = kt + 2;
                if (fs < KT)
                    fill_stage(A, B, M, N, lda, ldb, m0, n0, fs * 64,
                               sb + (fs % NSTAGE) * STAGE_BYTES, tid);
                asm volatile("cp.async.commit_group;" ::: "memory");
            }
        }
    }

    // epilogue
    const int r4 = lane >> 2, cp2 = (lane & 3) * 2;
    if (outHalf) {
        __half* C = (__half*)Cv + (long)bz * sC;
        const bool vec = ((ldc & 1) == 0);
#pragma unroll
        for (int mt = 0; mt < 4; mt++)
#pragma unroll
            for (int half_ = 0; half_ < 2; half_++) {
                const int m = m0 + wm * 64 + mt * 16 + r4 + half_ * 8;
                if (m >= M) continue;
                const long base = (long)m * ldc;
#pragma unroll
                for (int nt = 0; nt < 4; nt++) {
                    const int n = n0 + wn * 32 + nt * 8 + cp2;
                    if (n >= N) continue;
                    const float v0 = acc[mt][nt][half_ * 2 + 0] * alpha;
                    const float v1 = acc[mt][nt][half_ * 2 + 1] * alpha;
                    if (fuseV && n >= 1536) {
                        const int b = m / SEQ;
                        const int kk = m - b * SEQ;
                        __half* dst = vtOut + (long)b * DIM * SPAD
                                            + (long)(n - 1536) * SPAD + kk;
                        dst[0]    = __float2half_rn(v0);
                        dst[SPAD] = __float2half_rn(v1);
                    } else if (vec && (n + 1 < N)) {
                        *(__half2*)(C + base + n) = __floats2half2_rn(v0, v1);
                    } else {
                        C[base + n] = __float2half_rn(v0);
                        if (n + 1 < N) C[base + n + 1] = __float2half_rn(v1);
                    }
                }
            }
    } else {
        float* C = (float*)Cv + (long)bz * sC;
#pragma unroll
        for (int mt = 0; mt < 4; mt++)
#pragma unroll
            for (int half_ = 0; half_ < 2; half_++) {
                const int m = m0 + wm * 64 + mt * 16 + r4 + half_ * 8;
                if (m >= M) continue;
                const long base = (long)m * ldc;
#pragma unroll
                for (int nt = 0; nt < 4; nt++) {
                    const int n = n0 + wn * 32 + nt * 8 + cp2;
                    if (n >= N) continue;
                    float v0 = acc[mt][nt][half_ * 2 + 0] * alpha;
                    float v1 = acc[mt][nt][half_ * 2 + 1] * alpha;
                    if (bias) {
                        v0 += bias[n];
                        if (n + 1 < N) v1 += bias[n + 1];
                    }
                    if ((ldc & 1) == 0 && (n + 1 < N)) {
                        *(float2*)(C + base + n) = make_float2(v0, v1);
                    } else {
                        C[base + n] = v0;
                        if (n + 1 < N) C[base + n + 1] = v1;
                    }
                }
            }
    }
}

// ---------------- merged prologue: f2h x3 + vt pad zero ----------------
#define N1 ((long)ROWS * DIM / 4)
#define N2 ((long)QKVD * DIM / 4)
#define N3 ((long)DIM * DIM / 4)
#define N4 ((long)BB * DIM * 8)

__device__ __forceinline__ void cvt4(const float* __restrict__ in,
                                     __half* __restrict__ out, long i) {
    const float4 v = *(const float4*)(in + i * 4);
    *(__half2*)(out + i * 4)     = __floats2half2_rn(v.x, v.y);
    *(__half2*)(out + i * 4 + 2) = __floats2half2_rn(v.z, v.w);
}

__global__ void prologue_kernel(const float* __restrict__ x,
                                const float* __restrict__ wq,
                                const float* __restrict__ wp,
                                __half* __restrict__ xh,
                                __half* __restrict__ wqh,
                                __half* __restrict__ wph,
                                __half* __restrict__ vt) {
    long i = (long)blockIdx.x * blockDim.x + threadIdx.x;
    if (i < N1) { cvt4(x, xh, i); return; }
    i -= N1;
    if (i < N2) { cvt4(wq, wqh, i); return; }
    i -= N2;
    if (i < N3) { cvt4(wp, wph, i); return; }
    i -= N3;
    if (i < N4) {
        const long rc = i >> 3, j = i & 7;       // pad k in [576,640)
        *(float4*)(vt + rc * SPAD + 576 + j * 8) =
            make_float4(0.f, 0.f, 0.f, 0.f);
    }
}

// ---------------- softmax: fp32 -> fp16 P (+pad, +token-attn) ----------------
__global__ __launch_bounds__(256) void softmax_kernel(
    const float* __restrict__ S, __half* __restrict__ P, float* __restrict__ tok)
{
    const int row = blockIdx.x;
    const float* p = S + (long)row * SPAD;
    __half* o = P + (long)row * SPAD;
    const int tid = threadIdx.x;
    const int lane = tid & 31, wid = tid >> 5;
    __shared__ float red[8];

    float v[3];
    float m = -1e30f;
#pragma unroll
    for (int i = 0; i < 3; i++) {
        const int c = tid + i * 256;
        v[i] = (c < SEQ) ? p[c] : -1e30f;
        m = fmaxf(m, v[i]);
    }
#pragma unroll
    for (int off = 16; off > 0; off >>= 1)
        m = fmaxf(m, __shfl_xor_sync(0xFFFFFFFFu, m, off));
    if (lane == 0) red[wid] = m;
    __syncthreads();
    m = red[0];
#pragma unroll
    for (int i = 1; i < 8; i++) m = fmaxf(m, red[i]);
    __syncthreads();

    float sum = 0.f;
#pragma unroll
    for (int i = 0; i < 3; i++) {
        const int c = tid + i * 256;
        if (c < SEQ) { v[i] = __expf(v[i] - m); sum += v[i]; }
    }
#pragma unroll
    for (int off = 16; off > 0; off >>= 1)
        sum += __shfl_xor_sync(0xFFFFFFFFu, sum, off);
    if (lane == 0) red[wid] = sum;
    __syncthreads();
    sum = red[0];
#pragma unroll
    for (int i = 1; i < 8; i++) sum += red[i];
    const float inv = 1.0f / sum;

    const bool tokrow = ((row % SEQ) == 0);
    const int b = row / SEQ;
#pragma unroll
    for (int i = 0; i < 3; i++) {
        const int c = tid + i * 256;
        if (c < SEQ) {
            const float x = v[i] * inv;
            o[c] = __float2half_rn(x);
            if (tokrow && c >= 1) tok[(long)b * (SEQ - 1) + (c - 1)] = x;
        } else if (c < SPAD) {
            o[c] = __float2half_rn(0.f);
        }
    }
}

// ---------------------------------------------------------------------------
extern "C" void kernel_launch(void* const* d_in, const int* in_sizes, int n_in,
                              void* d_out, int out_size)
{
    const float* x      = (const float*)d_in[0];
    const float* w_qkv  = (const float*)d_in[1];
    const float* w_proj = (const float*)d_in[2];
    const float* b_proj = (const float*)d_in[3];
    float* out = (float*)d_out;
    float* tok = out + (size_t)ROWS * DIM;

    __half *xh, *wqh, *wph, *qkvh, *p, *vt, *yt;
    float *s;
    cudaGetSymbolAddress((void**)&xh,   g_xh);
    cudaGetSymbolAddress((void**)&wqh,  g_wqh);
    cudaGetSymbolAddress((void**)&wph,  g_wph);
    cudaGetSymbolAddress((void**)&qkvh, g_qkvh);
    cudaGetSymbolAddress((void**)&s,    g_s);
    cudaGetSymbolAddress((void**)&p,    g_p);
    cudaGetSymbolAddress((void**)&vt,   g_vt);
    cudaGetSymbolAddress((void**)&yt,   g_yt);

    cudaFuncSetAttribute(gemm_h, cudaFuncAttributeMaxDynamicSharedMemorySize, TC_SMEM);

    const float scale = 1.0f / sqrtf((float)DIM);

    // 0) merged prologue
    {
        const long total = N1 + N2 + N3 + N4;
        prologue_kernel<<<(int)((total + 255) / 256), 256>>>(
            x, w_qkv, w_proj, xh, wqh, wph, vt);
    }

    // 1) QKV (half out; V columns written transposed into vt)
    gemm_h<<<dim3(QKVD / 128, (ROWS + 127) / 128, 1), 256, TC_SMEM>>>(
        xh, wqh, qkvh, nullptr, ROWS, QKVD, DIM, DIM, DIM, QKVD,
        0, 0, 0, 1.0f, 1, 1, vt);

    // 2) S = scale * Q K^T (float out)
    gemm_h<<<dim3((SEQ + 127) / 128, (SEQ + 127) / 128, BB), 256, TC_SMEM>>>(
        qkvh, qkvh + DIM, s, nullptr, SEQ, SEQ, DIM, QKVD, QKVD, SPAD,
        (long)SEQ * QKVD, (long)SEQ * QKVD, (long)SEQ * SPAD, scale, 0, 0, nullptr);

    // 3) softmax -> fp16 P
    softmax_kernel<<<ROWS, 256>>>(s, p, tok);

    // 4) yt = Vt @ P^T (half out, transposed layout direct)
    gemm_h<<<dim3((SEQ + 127) / 128, DIM / 128, BB), 256, TC_SMEM>>>(
        vt, p, yt, nullptr, DIM, SEQ, SPAD, SPAD, SPAD, SEQ,
        (long)DIM * SPAD, (long)SEQ * SPAD, (long)DIM * SEQ, 1.0f, 1, 0, nullptr);

    // 5) out = Y2 @ Wproj^T + bias (float out)
    gemm_h<<<dim3(DIM / 128, (ROWS + 127) / 128, 1), 256, TC_SMEM>>>(
        yt, wph, out, b_proj, ROWS, DIM, DIM, DIM, DIM, DIM,
        0, 0, 0, 1.0f, 0, 0, nullptr);
}

// round 11
// speedup vs baseline: 7.3421x; 1.0353x over previous
#include <cuda_runtime.h>
#include <cuda_fp16.h>
#include <cstdint>
#include <math.h>

#define BB   32
#define SEQ  577
#define DIM  768
#define QKVD 2304
#define ROWS (BB * SEQ)      // 18464
#define SPAD 640

// ---------------- scratch ----------------
__device__ __half g_xh  [(size_t)ROWS * DIM];
__device__ __half g_wqh [(size_t)QKVD * DIM];
__device__ __half g_wph [(size_t)DIM * DIM];
__device__ __half g_qkvh[(size_t)ROWS * QKVD];
__device__ float  g_s   [(size_t)BB * SEQ * SPAD];
__device__ __half g_p   [(size_t)BB * SEQ * SPAD];
__device__ __half g_vt  [(size_t)BB * DIM * SPAD];
__device__ __half g_yt  [(size_t)BB * DIM * SEQ];

// ---------------- helpers ----------------
__device__ __forceinline__ uint32_t smem_u32(const void* p) {
    uint32_t a;
    asm("{ .reg .u64 t; cvta.to.shared.u64 t, %1; cvt.u32.u64 %0, t; }"
        : "=r"(a) : "l"(p));
    return a;
}
__device__ __forceinline__ void cpa16(uint32_t dst, const __half* src, bool ok) {
    int sz = ok ? 16 : 0;
    asm volatile("cp.async.cg.shared.global [%0], [%1], 16, %2;"
                 :: "r"(dst), "l"(src), "r"(sz));
}
__device__ __forceinline__ void ldsm4(uint32_t a, uint32_t* r) {
    asm volatile("ldmatrix.sync.aligned.m8n8.x4.shared.b16 {%0,%1,%2,%3}, [%4];"
                 : "=r"(r[0]), "=r"(r[1]), "=r"(r[2]), "=r"(r[3]) : "r"(a));
}
__device__ __forceinline__ void mma16(float* d, const uint32_t* a, const uint32_t* b) {
    asm volatile(
        "mma.sync.aligned.m16n8k16.row.col.f32.f16.f16.f32 "
        "{%0,%1,%2,%3}, {%4,%5,%6,%7}, {%8,%9}, {%0,%1,%2,%3};"
        : "+f"(d[0]), "+f"(d[1]), "+f"(d[2]), "+f"(d[3])
        : "r"(a[0]), "r"(a[1]), "r"(a[2]), "r"(a[3]), "r"(b[0]), "r"(b[1]));
}

// ---------------- tiling ----------------
#define STAGE_A 16384
#define STAGE_BYTES 32768
#define NSTAGE 3
#define TC_SMEM (NSTAGE * STAGE_BYTES)   // 96KB -> 2 CTAs/SM

__device__ __forceinline__ void fill_stage(
    const __half* __restrict__ A, const __half* __restrict__ B,
    int M, int N, int lda, int ldb, int m0, int n0, int k0,
    uint32_t st, int tid)
{
    const int q = tid & 7;
    const int r0 = tid >> 3;
    const int swq = (q ^ (r0 & 7)) << 4;
#pragma unroll
    for (int p = 0; p < 4; p++) {
        const int r = r0 + p * 32;
        {
            const int gr = m0 + r;
            const bool ok = gr < M;
            cpa16(st + r * 128 + swq, A + (long)(ok ? gr : 0) * lda + k0 + q * 8, ok);
        }
        {
            const int gr = n0 + r;
            const bool ok = gr < N;
            cpa16(st + STAGE_A + r * 128 + swq,
                  B + (long)(ok ? gr : 0) * ldb + k0 + q * 8, ok);
        }
    }
}

// ---------------------------------------------------------------------------
// NT GEMM, fp16 in, fp32 accum. outHalf=0: C float (+bias); 1: C half.
// fuseV: columns n >= 1536 are written transposed into vtOut.
// ---------------------------------------------------------------------------
__global__ __launch_bounds__(256, 2) void gemm_h(
    const __half* __restrict__ A, const __half* __restrict__ B,
    void* __restrict__ Cv, const float* __restrict__ bias,
    int M, int N, int K, int lda, int ldb, int ldc,
    long sA, long sB, long sC, float alpha, int outHalf,
    int fuseV, __half* __restrict__ vtOut)
{
    extern __shared__ char smem[];
    const uint32_t sb = smem_u32(smem);
    const int tid = threadIdx.x;
    const int wid = tid >> 5, lane = tid & 31;
    const int wm = wid & 1, wn = wid >> 1;      // warp tile 64(m) x 32(n)

    const int bz = blockIdx.z;
    A += (long)bz * sA;  B += (long)bz * sB;
    const int m0 = blockIdx.y * 128;
    const int n0 = blockIdx.x * 128;
    const int KT = K >> 6;

    const int a_row = lane & 15;
    const int a_co  = lane >> 4;
    const uint32_t a_base = (uint32_t)((wm * 64 + a_row) * 128 +
                                       ((a_co ^ (a_row & 7)) << 4));
    const int b_rowoff = ((lane >> 4) & 1) * 8 + (lane & 7);
    const int b_co     = (lane >> 3) & 1;
    const uint32_t b_base = (uint32_t)(STAGE_A + (wn * 32 + b_rowoff) * 128 +
                                       ((b_co ^ (b_rowoff & 7)) << 4));

    float acc[4][4][4];
#pragma unroll
    for (int i = 0; i < 4; i++)
#pragma unroll
        for (int j = 0; j < 4; j++)
#pragma unroll
            for (int r = 0; r < 4; r++) acc[i][j][r] = 0.f;

    fill_stage(A, B, M, N, lda, ldb, m0, n0, 0, sb, tid);
    asm volatile("cp.async.commit_group;" ::: "memory");
    if (KT > 1)
        fill_stage(A, B, M, N, lda, ldb, m0, n0, 64, sb + STAGE_BYTES, tid);
    asm volatile("cp.async.commit_group;" ::: "memory");

    for (int kt = 0; kt < KT; kt++) {
        asm volatile("cp.async.wait_group 1;" ::: "memory");
        __syncthreads();

        const uint32_t st = sb + (kt % NSTAGE) * STAGE_BYTES;

        uint32_t bf[2][2][4];                    // [buf][np][regs]
        ldsm4(st + b_base,        bf[0][0]);
        ldsm4(st + b_base + 2048, bf[0][1]);

#pragma unroll
        for (int s = 0; s < 4; s++) {
            const int cur = s & 1, nxt = cur ^ 1;
            if (s < 3) {                         // prefetch B for s+1
                const uint32_t kswn = (uint32_t)(2 * (s + 1)) << 4;
                const uint32_t bb2 = st + (b_base ^ kswn);
                ldsm4(bb2,        bf[nxt][0]);
                ldsm4(bb2 + 2048, bf[nxt][1]);
            }
            const uint32_t ksw = (uint32_t)(2 * s) << 4;
            const uint32_t ba = st + (a_base ^ ksw);
#pragma unroll
            for (int mtp = 0; mtp < 2; mtp++) {  // A in pairs (8 live regs)
                uint32_t af[2][4];
                ldsm4(ba + (2 * mtp) * 2048,     af[0]);
                ldsm4(ba + (2 * mtp + 1) * 2048, af[1]);
#pragma unroll
                for (int mi = 0; mi < 2; mi++) {
                    const int mt = 2 * mtp + mi;
#pragma unroll
                    for (int nt = 0; nt < 4; nt++)
                        mma16(acc[mt][nt], af[mi], &bf[cur][nt >> 1][(nt & 1) * 2]);
                }
            }
            if (s == 0) {                        // refill while s=1..3 compute
                const int fs = kt + 2;
                if (fs < KT)
                    fill_stage(A, B, M, N, lda, ldb, m0, n0, fs * 64,
                               sb + (fs % NSTAGE) * STAGE_BYTES, tid);
                asm volatile("cp.async.commit_group;" ::: "memory");
            }
        }
    }

    // epilogue
    const int r4 = lane >> 2, cp2 = (lane & 3) * 2;
    if (outHalf) {
        __half* C = (__half*)Cv + (long)bz * sC;
        const bool vec = ((ldc & 1) == 0);
#pragma unroll
        for (int mt = 0; mt < 4; mt++)
#pragma unroll
            for (int half_ = 0; half_ < 2; half_++) {
                const int m = m0 + wm * 64 + mt * 16 + r4 + half_ * 8;
                if (m >= M) continue;
                const long base = (long)m * ldc;
#pragma unroll
                for (int nt = 0; nt < 4; nt++) {
                    const int n = n0 + wn * 32 + nt * 8 + cp2;
                    if (n >= N) continue;
                    const float v0 = acc[mt][nt][half_ * 2 + 0] * alpha;
                    const float v1 = acc[mt][nt][half_ * 2 + 1] * alpha;
                    if (fuseV && n >= 1536) {
                        const int b = m / SEQ;
                        const int kk = m - b * SEQ;
                        __half* dst = vtOut + (long)b * DIM * SPAD
                                            + (long)(n - 1536) * SPAD + kk;
                        dst[0]    = __float2half_rn(v0);
                        dst[SPAD] = __float2half_rn(v1);
                    } else if (vec && (n + 1 < N)) {
                        *(__half2*)(C + base + n) = __floats2half2_rn(v0, v1);
                    } else {
                        C[base + n] = __float2half_rn(v0);
                        if (n + 1 < N) C[base + n + 1] = __float2half_rn(v1);
                    }
                }
            }
    } else {
        float* C = (float*)Cv + (long)bz * sC;
#pragma unroll
        for (int mt = 0; mt < 4; mt++)
#pragma unroll
            for (int half_ = 0; half_ < 2; half_++) {
                const int m = m0 + wm * 64 + mt * 16 + r4 + half_ * 8;
                if (m >= M) continue;
                const long base = (long)m * ldc;
#pragma unroll
                for (int nt = 0; nt < 4; nt++) {
                    const int n = n0 + wn * 32 + nt * 8 + cp2;
                    if (n >= N) continue;
                    float v0 = acc[mt][nt][half_ * 2 + 0] * alpha;
                    float v1 = acc[mt][nt][half_ * 2 + 1] * alpha;
                    if (bias) {
                        v0 += bias[n];
                        if (n + 1 < N) v1 += bias[n + 1];
                    }
                    if ((ldc & 1) == 0 && (n + 1 < N)) {
                        *(float2*)(C + base + n) = make_float2(v0, v1);
                    } else {
                        C[base + n] = v0;
                        if (n + 1 < N) C[base + n + 1] = v1;
                    }
                }
            }
    }
}

// ---------------- merged prologue: f2h x3 + vt pad zero ----------------
#define N1 ((long)ROWS * DIM / 4)
#define N2 ((long)QKVD * DIM / 4)
#define N3 ((long)DIM * DIM / 4)
#define N4 ((long)BB * DIM * 8)

__device__ __forceinline__ void cvt4(const float* __restrict__ in,
                                     __half* __restrict__ out, long i) {
    const float4 v = *(const float4*)(in + i * 4);
    *(__half2*)(out + i * 4)     = __floats2half2_rn(v.x, v.y);
    *(__half2*)(out + i * 4 + 2) = __floats2half2_rn(v.z, v.w);
}

__global__ void prologue_kernel(const float* __restrict__ x,
                                const float* __restrict__ wq,
                                const float* __restrict__ wp,
                                __half* __restrict__ xh,
                                __half* __restrict__ wqh,
                                __half* __restrict__ wph,
                                __half* __restrict__ vt) {
    long i = (long)blockIdx.x * blockDim.x + threadIdx.x;
    if (i < N1) { cvt4(x, xh, i); return; }
    i -= N1;
    if (i < N2) { cvt4(wq, wqh, i); return; }
    i -= N2;
    if (i < N3) { cvt4(wp, wph, i); return; }
    i -= N3;
    if (i < N4) {
        const long rc = i >> 3, j = i & 7;       // pad k in [576,640)
        *(float4*)(vt + rc * SPAD + 576 + j * 8) =
            make_float4(0.f, 0.f, 0.f, 0.f);
    }
}

// ---------------- softmax: one warp per row, barrier-free -------------------
// Each warp: 5 float4/lane covers 640 floats. Out-of-range -> -1e30 so exp=0,
// which also produces the zero K-pad in P for free.
__global__ __launch_bounds__(256) void softmax_kernel(
    const float* __restrict__ S, __half* __restrict__ P, float* __restrict__ tok)
{
    const int row  = (blockIdx.x << 3) | (threadIdx.x >> 5);
    const int lane = threadIdx.x & 31;
    const float* p = S + (long)row * SPAD;
    __half* o = P + (long)row * SPAD;

    float4 v[5];
    float m = -1e30f;
#pragma unroll
    for (int j = 0; j < 5; j++) {
        const int c0 = (lane + (j << 5)) << 2;
        float4 t = *(const float4*)(p + c0);
        t.x = (c0 + 0 < SEQ) ? t.x : -1e30f;
        t.y = (c0 + 1 < SEQ) ? t.y : -1e30f;
        t.z = (c0 + 2 < SEQ) ? t.z : -1e30f;
        t.w = (c0 + 3 < SEQ) ? t.w : -1e30f;
        v[j] = t;
        m = fmaxf(m, fmaxf(fmaxf(t.x, t.y), fmaxf(t.z, t.w)));
    }
#pragma unroll
    for (int off = 16; off > 0; off >>= 1)
        m = fmaxf(m, __shfl_xor_sync(0xFFFFFFFFu, m, off));

    float sum = 0.f;
#pragma unroll
    for (int j = 0; j < 5; j++) {
        v[j].x = __expf(v[j].x - m);
        v[j].y = __expf(v[j].y - m);
        v[j].z = __expf(v[j].z - m);
        v[j].w = __expf(v[j].w - m);
        sum += (v[j].x + v[j].y) + (v[j].z + v[j].w);
    }
#pragma unroll
    for (int off = 16; off > 0; off >>= 1)
        sum += __shfl_xor_sync(0xFFFFFFFFu, sum, off);
    const float inv = 1.0f / sum;

#pragma unroll
    for (int j = 0; j < 5; j++) {
        const int c0 = (lane + (j << 5)) << 2;
        const float x0 = v[j].x * inv, x1 = v[j].y * inv;
        const float x2 = v[j].z * inv, x3 = v[j].w * inv;
        *(__half2*)(o + c0)     = __floats2half2_rn(x0, x1);
        *(__half2*)(o + c0 + 2) = __floats2half2_rn(x2, x3);
    }

    if ((row % SEQ) == 0) {                      // token-attn extraction
        const int b = row / SEQ;
        float* t = tok + (long)b * (SEQ - 1);
#pragma unroll
        for (int j = 0; j < 5; j++) {
            const int c0 = (lane + (j << 5)) << 2;
            const float xs[4] = {v[j].x * inv, v[j].y * inv,
                                 v[j].z * inv, v[j].w * inv};
#pragma unroll
            for (int q = 0; q < 4; q++) {
                const int c = c0 + q;
                if (c >= 1 && c < SEQ) t[c - 1] = xs[q];
            }
        }
    }
}

// ---------------------------------------------------------------------------
extern "C" void kernel_launch(void* const* d_in, const int* in_sizes, int n_in,
                              void* d_out, int out_size)
{
    const float* x      = (const float*)d_in[0];
    const float* w_qkv  = (const float*)d_in[1];
    const float* w_proj = (const float*)d_in[2];
    const float* b_proj = (const float*)d_in[3];
    float* out = (float*)d_out;
    float* tok = out + (size_t)ROWS * DIM;

    __half *xh, *wqh, *wph, *qkvh, *p, *vt, *yt;
    float *s;
    cudaGetSymbolAddress((void**)&xh,   g_xh);
    cudaGetSymbolAddress((void**)&wqh,  g_wqh);
    cudaGetSymbolAddress((void**)&wph,  g_wph);
    cudaGetSymbolAddress((void**)&qkvh, g_qkvh);
    cudaGetSymbolAddress((void**)&s,    g_s);
    cudaGetSymbolAddress((void**)&p,    g_p);
    cudaGetSymbolAddress((void**)&vt,   g_vt);
    cudaGetSymbolAddress((void**)&yt,   g_yt);

    cudaFuncSetAttribute(gemm_h, cudaFuncAttributeMaxDynamicSharedMemorySize, TC_SMEM);

    const float scale = 1.0f / sqrtf((float)DIM);

    // 0) merged prologue
    {
        const long total = N1 + N2 + N3 + N4;
        prologue_kernel<<<(int)((total + 255) / 256), 256>>>(
            x, w_qkv, w_proj, xh, wqh, wph, vt);
    }

    // 1) QKV (half out; V columns written transposed into vt)
    gemm_h<<<dim3(QKVD / 128, (ROWS + 127) / 128, 1), 256, TC_SMEM>>>(
        xh, wqh, qkvh, nullptr, ROWS, QKVD, DIM, DIM, DIM, QKVD,
        0, 0, 0, 1.0f, 1, 1, vt);

    // 2) S = scale * Q K^T (float out)
    gemm_h<<<dim3((SEQ + 127) / 128, (SEQ + 127) / 128, BB), 256, TC_SMEM>>>(
        qkvh, qkvh + DIM, s, nullptr, SEQ, SEQ, DIM, QKVD, QKVD, SPAD,
        (long)SEQ * QKVD, (long)SEQ * QKVD, (long)SEQ * SPAD, scale, 0, 0, nullptr);

    // 3) softmax -> fp16 P  (one warp per row; ROWS = 2308 * 8)
    softmax_kernel<<<ROWS / 8, 256>>>(s, p, tok);

    // 4) yt = Vt @ P^T (half out, transposed layout direct)
    gemm_h<<<dim3((SEQ + 127) / 128, DIM / 128, BB), 256, TC_SMEM>>>(
        vt, p, yt, nullptr, DIM, SEQ, SPAD, SPAD, SPAD, SEQ,
        (long)DIM * SPAD, (long)SEQ * SPAD, (long)DIM * SEQ, 1.0f, 1, 0, nullptr);

    // 5) out = Y2 @ Wproj^T + bias (float out)
    gemm_h<<<dim3(DIM / 128, (ROWS + 127) / 128, 1), 256, TC_SMEM>>>(
        yt, wph, out, b_proj, ROWS, DIM, DIM, DIM, DIM, DIM,
        0, 0, 0, 1.0f, 0, 0, nullptr);
}